// round 10
// baseline (speedup 1.0000x reference)
#include <cuda_runtime.h>
#include <cuda_fp16.h>
#include <math.h>
#include <stdint.h>

// Problem constants
#define NB  2
#define NS  2048
#define ND  1024
#define NH  16
#define NHD 64
#define SCALE  0.125f    // 1/sqrt(64), applied to scores post-MMA
#define WSCALE 32.0f     // weight pre-scale (keeps w_lo out of fp16 subnormals)
#define INVW   0.03125f

// ---------------------------------------------------------------------------
// Scratch (allocation-free contract: __device__ globals)
// ---------------------------------------------------------------------------
__device__ __half g_qh[NB * NH * NS * NHD];   // [bh][s][hd]  (unscaled hi)
__device__ __half g_ql[NB * NH * NS * NHD];
__device__ __half g_kh[NB * NH * NS * NHD];   // [bh][s][hd]
__device__ __half g_kl[NB * NH * NS * NHD];
__device__ __half g_vh[NB * NH * NS * NHD];   // [bh][hd][s]  (transposed)
__device__ __half g_vl[NB * NH * NS * NHD];
__device__ __half g_axh[NB * NS * ND];        // activation hi/lo (x, then attn out)
__device__ __half g_axl[NB * NS * ND];
__device__ __half g_wqh[3 * ND * ND];         // W_qkv^T * 32, hi   [3072 x 1024]
__device__ __half g_wql[3 * ND * ND];
__device__ __half g_wph[ND * ND];             // W_proj^T * 32, hi  [1024 x 1024]
__device__ __half g_wpl[ND * ND];

// ---------------------------------------------------------------------------
// Helpers
// ---------------------------------------------------------------------------
__device__ __forceinline__ uint32_t smem_u32(const void* p) {
    uint32_t a;
    asm("{ .reg .u64 t; cvta.to.shared.u64 t, %1; cvt.u32.u64 %0, t; }"
        : "=r"(a) : "l"(p));
    return a;
}

__device__ __forceinline__ void cp_async16(uint32_t saddr, const void* gptr) {
    asm volatile("cp.async.cg.shared.global [%0], [%1], 16;" :: "r"(saddr), "l"(gptr));
}
#define CP_COMMIT() asm volatile("cp.async.commit_group;" ::: "memory")

__device__ __forceinline__ uint32_t ldh2(const __half* p) {
    return *reinterpret_cast<const uint32_t*>(p);
}

__device__ __forceinline__ uint32_t pack_h2(float a, float b) {
    __half2 h = __floats2half2_rn(a, b);
    return *reinterpret_cast<uint32_t*>(&h);
}

__device__ __forceinline__ void split_h(float v, __half& hi, __half& lo) {
    hi = __float2half_rn(v);
    lo = __float2half_rn(v - __half2float(hi));
}

__device__ __forceinline__ float2 h2f2(uint32_t u) {
    __half2 h = *reinterpret_cast<__half2*>(&u);
    return __half22float2(h);
}

// ldmatrix: 4x (8x8 b16) tiles; per-lane row addresses
__device__ __forceinline__ void ldsm_x4(uint32_t& r0, uint32_t& r1,
                                        uint32_t& r2, uint32_t& r3, uint32_t addr) {
    asm volatile("ldmatrix.sync.aligned.m8n8.x4.shared.b16 {%0,%1,%2,%3}, [%4];"
        : "=r"(r0), "=r"(r1), "=r"(r2), "=r"(r3) : "r"(addr));
}

// m16n8k16 f16 MMA, fp32 accumulate in-place
__device__ __forceinline__ void mma_f16(float* d, const uint32_t* a, const uint32_t* b) {
    asm volatile(
        "mma.sync.aligned.m16n8k16.row.col.f32.f16.f16.f32 "
        "{%0,%1,%2,%3}, {%4,%5,%6,%7}, {%8,%9}, {%0,%1,%2,%3};"
        : "+f"(d[0]), "+f"(d[1]), "+f"(d[2]), "+f"(d[3])
        : "r"(a[0]), "r"(a[1]), "r"(a[2]), "r"(a[3]), "r"(b[0]), "r"(b[1]));
}

// m16n8k16 f16 MMA, fp16 accumulate in-place (full-rate path)
__device__ __forceinline__ void mma_f16acc(uint32_t* d, const uint32_t* a, const uint32_t* b) {
    asm volatile(
        "mma.sync.aligned.m16n8k16.row.col.f16.f16.f16.f16 "
        "{%0,%1}, {%2,%3,%4,%5}, {%6,%7}, {%0,%1};"
        : "+r"(d[0]), "+r"(d[1])
        : "r"(a[0]), "r"(a[1]), "r"(a[2]), "r"(a[3]), "r"(b[0]), "r"(b[1]));
}

// FFMA-only exp (finite x; clamp handles big negatives). rel err ~2.4e-6.
__device__ __forceinline__ float fexp(float x) {
    x = fmaxf(x, -60.0f);
    const float y = x * 1.44269504f;
    const float t = y + 12582912.0f;              // 1.5 * 2^23
    const int   n = __float_as_int(t) - 0x4B400000;
    const float f = y - (t - 12582912.0f);
    float p = 1.33335581e-3f;
    p = fmaf(p, f, 9.61812910e-3f);
    p = fmaf(p, f, 5.55041087e-2f);
    p = fmaf(p, f, 2.40226510e-1f);
    p = fmaf(p, f, 6.93147182e-1f);
    p = fmaf(p, f, 1.0f);
    return __int_as_float(__float_as_int(p) + (n << 23));
}

// ---------------------------------------------------------------------------
// Prep kernels
// ---------------------------------------------------------------------------
__global__ void split16_kernel(const float* __restrict__ in,
                               __half* __restrict__ hi, __half* __restrict__ lo, int n) {
    for (int i = blockIdx.x * blockDim.x + threadIdx.x; i < n; i += gridDim.x * blockDim.x) {
        __half h, l;
        split_h(in[i], h, l);
        hi[i] = h;
        lo[i] = l;
    }
}

// W [K,N] row-major -> T [N,K] row-major, scaled by WSCALE, fp16 hi/lo split
__global__ __launch_bounds__(256) void tsplit16_kernel(
    const float* __restrict__ W, __half* __restrict__ Thi, __half* __restrict__ Tlo,
    int K, int N) {
    __shared__ float tile[32][33];
    const int tx = threadIdx.x;
    const int ty = threadIdx.y;
    const int n0 = blockIdx.x * 32;
    const int k0 = blockIdx.y * 32;
#pragma unroll
    for (int i = 0; i < 32; i += 8)
        tile[ty + i][tx] = W[(size_t)(k0 + ty + i) * N + n0 + tx];
    __syncthreads();
#pragma unroll
    for (int i = 0; i < 32; i += 8) {
        float v = tile[tx][ty + i] * WSCALE;
        __half h, l;
        split_h(v, h, l);
        Thi[(size_t)(n0 + ty + i) * K + k0 + tx] = h;
        Tlo[(size_t)(n0 + ty + i) * K + k0 + tx] = l;
    }
}

// ---------------------------------------------------------------------------
// FP16x2 mma.sync GEMM: hi*hi in fp32 acc (half-rate), hi*lo + lo*hi share
// one fp16 acc (full-rate).  C[M,N] = (A*B^T)/32.  128x128/CTA, 256 threads,
// warps 2(m) x 4(n), warp tile 64x32, KC 64, double-buffered cp.async.
// MODE 0: split-scatter QKV;  MODE 1: C = acc/32 + bias (fp32)
// ---------------------------------------------------------------------------
#define KC     64
#define ROWH   72                       // 64 + 8 halves pad
#define TILEH  (128 * ROWH)             // halves per tile
#define STAGEH (4 * TILEH)              // Ah, Al, Bh, Bl
#define GEMM_SMEM (2 * STAGEH * 2)      // bytes = 147456

template <int MODE>
__global__ __launch_bounds__(256, 1) void gemm_f16(
    const __half* __restrict__ Ahi, const __half* __restrict__ Alo,
    const __half* __restrict__ Bhi, const __half* __restrict__ Blo,
    const float* __restrict__ bias, float* __restrict__ C,
    int M, int N, int K)
{
    extern __shared__ __half smh[];
    const int tid  = threadIdx.x;
    const int lane = tid & 31;
    const int wid  = tid >> 5;
    const int wm   = wid >> 2;
    const int wn   = wid & 3;
    const int g    = lane >> 2;
    const int tg   = lane & 3;
    const int bm = blockIdx.y * 128;
    const int bn = blockIdx.x * 128;

    // ldmatrix per-lane byte offsets (within a 16x16 tile at given base)
    const int la = lane & 7;
    const uint32_t aoff = (uint32_t)(((la + ((lane >> 3) & 1) * 8) * ROWH
                                     + ((lane >> 4) & 1) * 8) * 2);
    const uint32_t boff = (uint32_t)(((la + ((lane >> 4) & 1) * 8) * ROWH
                                     + ((lane >> 3) & 1) * 8) * 2);

    const __half* srcT[4] = {Ahi, Alo, Bhi, Blo};

    auto load_stage = [&](int c, int s) {
        const int k0 = c * KC;
        __half* stage = smh + s * STAGEH;
#pragma unroll
        for (int t = 0; t < 4; t++) {
            const __half* src = srcT[t];
            const int rbase = (t < 2) ? bm : bn;
            __half* dst = stage + t * TILEH;
#pragma unroll
            for (int i = 0; i < 4; i++) {
                const int idx = tid + i * 256;     // 0..1023
                const int r = idx >> 3;
                const int q = idx & 7;             // 8 halves (16B) per chunk
                cp_async16(smem_u32(dst + r * ROWH + q * 8),
                           src + (size_t)(rbase + r) * K + k0 + q * 8);
            }
        }
        CP_COMMIT();
    };

    float acc[4][4][4];
    uint32_t acch[4][4][2];              // shared fp16 accumulator for both corrections
#pragma unroll
    for (int i = 0; i < 4; i++)
#pragma unroll
        for (int j = 0; j < 4; j++) {
#pragma unroll
            for (int kq = 0; kq < 4; kq++) acc[i][j][kq] = 0.f;
            acch[i][j][0] = 0u; acch[i][j][1] = 0u;
        }

    const int NCH = K / KC;
    load_stage(0, 0);

    for (int c = 0; c < NCH; c++) {
        const int s = c & 1;
        if (c + 1 < NCH) {
            load_stage(c + 1, (c + 1) & 1);
            asm volatile("cp.async.wait_group 1;" ::: "memory");
        } else {
            asm volatile("cp.async.wait_group 0;" ::: "memory");
        }
        __syncthreads();

        const uint32_t sA = smem_u32(smh + s * STAGEH);          // Ah
        const uint32_t sB = sA + 2 * TILEH * 2;                  // Bh (bytes)

#pragma unroll
        for (int ks = 0; ks < 4; ks++) {
            const int kb = ks * 16;
            uint32_t ah[4][4], al[4][4], bh[4][2], bl[4][2];
#pragma unroll
            for (int am = 0; am < 4; am++) {
                const uint32_t base = sA + (uint32_t)(((wm * 64 + am * 16) * ROWH + kb) * 2);
                ldsm_x4(ah[am][0], ah[am][1], ah[am][2], ah[am][3], base + aoff);
                ldsm_x4(al[am][0], al[am][1], al[am][2], al[am][3],
                        base + (uint32_t)(TILEH * 2) + aoff);
            }
#pragma unroll
            for (int p = 0; p < 2; p++) {
                const uint32_t base = sB + (uint32_t)(((wn * 32 + p * 16) * ROWH + kb) * 2);
                ldsm_x4(bh[2 * p][0], bh[2 * p][1], bh[2 * p + 1][0], bh[2 * p + 1][1],
                        base + boff);
                ldsm_x4(bl[2 * p][0], bl[2 * p][1], bl[2 * p + 1][0], bl[2 * p + 1][1],
                        base + (uint32_t)(TILEH * 2) + boff);
            }
            // main product: fp32 accumulators (half-rate path)
#pragma unroll
            for (int am = 0; am < 4; am++)
#pragma unroll
                for (int an = 0; an < 4; an++)
                    mma_f16(acc[am][an], ah[am], bh[an]);
            // corrections: shared fp16 accumulator (full-rate path)
#pragma unroll
            for (int am = 0; am < 4; am++)
#pragma unroll
                for (int an = 0; an < 4; an++)
                    mma_f16acc(acch[am][an], ah[am], bl[an]);
#pragma unroll
            for (int am = 0; am < 4; am++)
#pragma unroll
                for (int an = 0; an < 4; an++)
                    mma_f16acc(acch[am][an], al[am], bh[an]);
        }
        __syncthreads();
    }

    // ---- epilogue: combine fp32 main + fp16 corrections ----
#pragma unroll
    for (int am = 0; am < 4; am++) {
        const int row0 = bm + wm * 64 + am * 16 + g;
#pragma unroll
        for (int an = 0; an < 4; an++) {
            const int col = bn + wn * 32 + an * 8 + 2 * tg;
            const float2 c01 = h2f2(acch[am][an][0]);
            const float2 c23 = h2f2(acch[am][an][1]);
            const float v00 = (acc[am][an][0] + c01.x) * INVW + bias[col];
            const float v01 = (acc[am][an][1] + c01.y) * INVW + bias[col + 1];
            const float v10 = (acc[am][an][2] + c23.x) * INVW + bias[col];
            const float v11 = (acc[am][an][3] + c23.y) * INVW + bias[col + 1];
            if (MODE == 0) {
#pragma unroll
                for (int e = 0; e < 4; e++) {
                    const int m = (e < 2) ? row0 : row0 + 8;
                    const int n = col + (e & 1);
                    const float v = (e == 0) ? v00 : (e == 1) ? v01 : (e == 2) ? v10 : v11;
                    const int b = m >> 11;            // NS = 2048
                    const int srow = m & (NS - 1);
                    const int which = n >> 10;        // ND = 1024
                    const int dcol  = n & (ND - 1);
                    const int h  = dcol >> 6;         // NHD = 64
                    const int hd = dcol & 63;
                    const int bhh = b * NH + h;
                    __half hi, lo;
                    split_h(v, hi, lo);
                    if (which == 0) {
                        const size_t o = ((size_t)bhh * NS + srow) * NHD + hd;
                        g_qh[o] = hi; g_ql[o] = lo;
                    } else if (which == 1) {
                        const size_t o = ((size_t)bhh * NS + srow) * NHD + hd;
                        g_kh[o] = hi; g_kl[o] = lo;
                    } else {
                        const size_t o = ((size_t)bhh * NHD + hd) * NS + srow;
                        g_vh[o] = hi; g_vl[o] = lo;
                    }
                }
            } else {
                *(float2*)(C + (size_t)row0 * N + col)       = make_float2(v00, v01);
                *(float2*)(C + (size_t)(row0 + 8) * N + col) = make_float2(v10, v11);
            }
        }
    }
}

// ---------------------------------------------------------------------------
// FP16 tensor-core causal flash attention (ldmatrix + fp16-acc corrections).
// CTA: 128 q rows, 256 threads = 8 warps (one m16 band each), KV tiles of 64.
// ---------------------------------------------------------------------------
#define AST    72                       // 64 + 8 halves pad
#define TILE_A (64 * AST)               // halves per tile
#define STG_H  (4 * TILE_A)             // Kh, Kl, Vh, Vl
#define ATTN_SMEM (2 * STG_H * 2)       // bytes = 73728

__global__ __launch_bounds__(256, 1) void attn_f16()
{
    extern __shared__ __half smh[];
    const int tid  = threadIdx.x;
    const int lane = tid & 31;
    const int w    = tid >> 5;
    const int g    = lane >> 2;
    const int tg   = lane & 3;
    const int qt   = 15 - blockIdx.x;      // heavy CTAs first
    const int bh   = blockIdx.y;
    const int qbase = qt * 128;

    const int la = lane & 7;
    const uint32_t boff = (uint32_t)(((la + ((lane >> 4) & 1) * 8) * AST
                                     + ((lane >> 3) & 1) * 8) * 2);

    const __half* Qh = g_qh + (size_t)bh * NS * NHD;
    const __half* Ql = g_ql + (size_t)bh * NS * NHD;
    const __half* Kh = g_kh + (size_t)bh * NS * NHD;
    const __half* Kl = g_kl + (size_t)bh * NS * NHD;
    const __half* Vh = g_vh + (size_t)bh * NHD * NS;
    const __half* Vl = g_vl + (size_t)bh * NHD * NS;

    const int r0 = qbase + w * 16 + g;     // global q row of accum row 0

    // Q fragments resident in registers (4 ksteps of k16)
    uint32_t qfh[4][4], qfl[4][4];
#pragma unroll
    for (int ks = 0; ks < 4; ks++) {
        const int kb = ks * 16;
        qfh[ks][0] = ldh2(Qh + (size_t)r0 * NHD + kb + 2 * tg);
        qfh[ks][1] = ldh2(Qh + (size_t)(r0 + 8) * NHD + kb + 2 * tg);
        qfh[ks][2] = ldh2(Qh + (size_t)r0 * NHD + kb + 8 + 2 * tg);
        qfh[ks][3] = ldh2(Qh + (size_t)(r0 + 8) * NHD + kb + 8 + 2 * tg);
        qfl[ks][0] = ldh2(Ql + (size_t)r0 * NHD + kb + 2 * tg);
        qfl[ks][1] = ldh2(Ql + (size_t)(r0 + 8) * NHD + kb + 2 * tg);
        qfl[ks][2] = ldh2(Ql + (size_t)r0 * NHD + kb + 8 + 2 * tg);
        qfl[ks][3] = ldh2(Ql + (size_t)(r0 + 8) * NHD + kb + 8 + 2 * tg);
    }

    float o[8][4];
#pragma unroll
    for (int j = 0; j < 8; j++)
#pragma unroll
        for (int c = 0; c < 4; c++) o[j][c] = 0.f;
    float m[2] = {-1e30f, -1e30f};
    float l[2] = {0.f, 0.f};

    const int nt = 2 * qt + 2;

    auto load_tile = [&](int kt, int s) {
        __half* st = smh + s * STG_H;
#pragma unroll
        for (int i = 0; i < 2; i++) {
            const int idx = tid + i * 256;       // 0..511
            const int row = idx >> 3;            // 0..63
            const int q   = idx & 7;             // 8-half chunk
            const uint32_t d = smem_u32(st + row * AST + q * 8);
            cp_async16(d,                  Kh + (size_t)(kt * 64 + row) * NHD + q * 8);
            cp_async16(d + TILE_A * 2,     Kl + (size_t)(kt * 64 + row) * NHD + q * 8);
            cp_async16(d + 2 * TILE_A * 2, Vh + (size_t)row * NS + kt * 64 + q * 8);
            cp_async16(d + 3 * TILE_A * 2, Vl + (size_t)row * NS + kt * 64 + q * 8);
        }
        CP_COMMIT();
    };

    load_tile(0, 0);

    for (int kt = 0; kt < nt; kt++) {
        const int s = kt & 1;
        __syncthreads();                        // all warps done with stage s^1
        if (kt + 1 < nt) {
            load_tile(kt + 1, s ^ 1);
            asm volatile("cp.async.wait_group 1;" ::: "memory");
        } else {
            asm volatile("cp.async.wait_group 0;" ::: "memory");
        }
        __syncthreads();                        // stage s visible to all

        const uint32_t sK = smem_u32(smh + s * STG_H);           // Kh (bytes)
        const uint32_t sV = sK + 2 * TILE_A * 2;                 // Vh

        // ---- S = Q K^T : hi*hi fp32 acc; corrections in fp16 acc ----
        float sc[8][4];
        uint32_t scch[8][2];
#pragma unroll
        for (int j = 0; j < 8; j++) {
#pragma unroll
            for (int c = 0; c < 4; c++) sc[j][c] = 0.f;
            scch[j][0] = 0u; scch[j][1] = 0u;
        }

#pragma unroll
        for (int ks = 0; ks < 4; ks++) {
            const int kb = ks * 16;
            uint32_t bfh[8][2], bfl[8][2];
#pragma unroll
            for (int p = 0; p < 4; p++) {
                const uint32_t base = sK + (uint32_t)((p * 16 * AST + kb) * 2);
                ldsm_x4(bfh[2 * p][0], bfh[2 * p][1], bfh[2 * p + 1][0], bfh[2 * p + 1][1],
                        base + boff);
                ldsm_x4(bfl[2 * p][0], bfl[2 * p][1], bfl[2 * p + 1][0], bfl[2 * p + 1][1],
                        base + (uint32_t)(TILE_A * 2) + boff);
            }
#pragma unroll
            for (int j = 0; j < 8; j++) mma_f16(sc[j], qfh[ks], bfh[j]);
#pragma unroll
            for (int j = 0; j < 8; j++) mma_f16acc(scch[j], qfh[ks], bfl[j]);
#pragma unroll
            for (int j = 0; j < 8; j++) mma_f16acc(scch[j], qfl[ks], bfh[j]);
        }

        // ---- fold corrections, scale, causal mask ----
#pragma unroll
        for (int j = 0; j < 8; j++) {
            const float2 c01 = h2f2(scch[j][0]);
            const float2 c23 = h2f2(scch[j][1]);
            sc[j][0] = (sc[j][0] + c01.x) * SCALE;
            sc[j][1] = (sc[j][1] + c01.y) * SCALE;
            sc[j][2] = (sc[j][2] + c23.x) * SCALE;
            sc[j][3] = (sc[j][3] + c23.y) * SCALE;
        }
        if (kt >= 2 * qt) {
            const int colb = kt * 64;
#pragma unroll
            for (int j = 0; j < 8; j++) {
                const int c0 = colb + j * 8 + 2 * tg;
#pragma unroll
                for (int c = 0; c < 4; c++) {
                    const int col = c0 + (c & 1);
                    const int row = (c < 2) ? r0 : r0 + 8;
                    if (col > row) sc[j][c] = -1e30f;
                }
            }
        }

        // ---- online softmax (FFMA exp) ----
#pragma unroll
        for (int r = 0; r < 2; r++) {
            float rm = -1e30f;
#pragma unroll
            for (int j = 0; j < 8; j++)
                rm = fmaxf(rm, fmaxf(sc[j][2 * r], sc[j][2 * r + 1]));
            rm = fmaxf(rm, __shfl_xor_sync(0xffffffffu, rm, 1));
            rm = fmaxf(rm, __shfl_xor_sync(0xffffffffu, rm, 2));
            const float mn   = fmaxf(m[r], rm);
            const float corr = fexp(m[r] - mn);
            m[r] = mn;
            float ps = 0.f;
#pragma unroll
            for (int j = 0; j < 8; j++) {
                const float p0 = fexp(sc[j][2 * r]     - mn);
                const float p1 = fexp(sc[j][2 * r + 1] - mn);
                sc[j][2 * r]     = p0;
                sc[j][2 * r + 1] = p1;
                ps += p0 + p1;
            }
            l[r] = l[r] * corr + ps;
#pragma unroll
            for (int j = 0; j < 8; j++) {
                o[j][2 * r]     *= corr;
                o[j][2 * r + 1] *= corr;
            }
        }

        // ---- O += P V : Vh pass fp32 acc; Vl pass per-tile fp16 acc ----
        uint32_t och[8][2];
#pragma unroll
        for (int j = 0; j < 8; j++) { och[j][0] = 0u; och[j][1] = 0u; }
#pragma unroll
        for (int ks = 0; ks < 4; ks++) {
            const int kb = ks * 16;
            uint32_t pa[4];
            pa[0] = pack_h2(sc[2 * ks][0],     sc[2 * ks][1]);
            pa[1] = pack_h2(sc[2 * ks][2],     sc[2 * ks][3]);
            pa[2] = pack_h2(sc[2 * ks + 1][0], sc[2 * ks + 1][1]);
            pa[3] = pack_h2(sc[2 * ks + 1][2], sc[2 * ks + 1][3]);
            uint32_t vfh[8][2], vfl[8][2];
#pragma unroll
            for (int p = 0; p < 4; p++) {
                const uint32_t base = sV + (uint32_t)((p * 16 * AST + kb) * 2);
                ldsm_x4(vfh[2 * p][0], vfh[2 * p][1], vfh[2 * p + 1][0], vfh[2 * p + 1][1],
                        base + boff);
                ldsm_x4(vfl[2 * p][0], vfl[2 * p][1], vfl[2 * p + 1][0], vfl[2 * p + 1][1],
                        base + (uint32_t)(TILE_A * 2) + boff);
            }
#pragma unroll
            for (int j = 0; j < 8; j++) mma_f16(o[j], pa, vfh[j]);
#pragma unroll
            for (int j = 0; j < 8; j++) mma_f16acc(och[j], pa, vfl[j]);
        }
#pragma unroll
        for (int j = 0; j < 8; j++) {
            const float2 c01 = h2f2(och[j][0]);
            const float2 c23 = h2f2(och[j][1]);
            o[j][0] += c01.x; o[j][1] += c01.y;
            o[j][2] += c23.x; o[j][3] += c23.y;
        }
    }

    // ---- finalize: normalize, split to fp16 hi/lo, write [b,s,d] ----
#pragma unroll
    for (int r = 0; r < 2; r++) {
        float lv = l[r];
        lv += __shfl_xor_sync(0xffffffffu, lv, 1);
        lv += __shfl_xor_sync(0xffffffffu, lv, 2);
        l[r] = 1.0f / lv;
    }
    const int b = bh >> 4;
    const int h = bh & (NH - 1);
#pragma unroll
    for (int j = 0; j < 8; j++) {
        const int col = h * NHD + j * 8 + 2 * tg;
#pragma unroll
        for (int r = 0; r < 2; r++) {
            const int row = (r == 0) ? r0 : r0 + 8;
            const size_t off = ((size_t)(b * NS) + row) * ND + col;
            const float v0 = o[j][2 * r]     * l[r];
            const float v1 = o[j][2 * r + 1] * l[r];
            __half h0, l0, h1, l1;
            split_h(v0, h0, l0);
            split_h(v1, h1, l1);
            *(uint32_t*)(g_axh + off) = (uint32_t)__half_as_ushort(h0) | ((uint32_t)__half_as_ushort(h1) << 16);
            *(uint32_t*)(g_axl + off) = (uint32_t)__half_as_ushort(l0) | ((uint32_t)__half_as_ushort(l1) << 16);
        }
    }
}

// ---------------------------------------------------------------------------
// kernel_launch
// ---------------------------------------------------------------------------
extern "C" void kernel_launch(void* const* d_in, const int* in_sizes, int n_in,
                              void* d_out, int out_size)
{
    (void)in_sizes; (void)n_in; (void)out_size;
    const float* x     = (const float*)d_in[0];
    const float* Wqkv  = (const float*)d_in[1];
    const float* bqkv  = (const float*)d_in[2];
    const float* Wproj = (const float*)d_in[3];
    const float* bproj = (const float*)d_in[4];
    float* out = (float*)d_out;

    void *p_axh, *p_axl, *p_wqh, *p_wql, *p_wph, *p_wpl;
    cudaGetSymbolAddress(&p_axh, g_axh);
    cudaGetSymbolAddress(&p_axl, g_axl);
    cudaGetSymbolAddress(&p_wqh, g_wqh);
    cudaGetSymbolAddress(&p_wql, g_wql);
    cudaGetSymbolAddress(&p_wph, g_wph);
    cudaGetSymbolAddress(&p_wpl, g_wpl);
    __half* axh = (__half*)p_axh; __half* axl = (__half*)p_axl;
    __half* wqh = (__half*)p_wqh; __half* wql = (__half*)p_wql;
    __half* wph = (__half*)p_wph; __half* wpl = (__half*)p_wpl;

    static bool attr_done = false;
    if (!attr_done) {
        cudaFuncSetAttribute((const void*)gemm_f16<0>,
                             cudaFuncAttributeMaxDynamicSharedMemorySize, GEMM_SMEM);
        cudaFuncSetAttribute((const void*)gemm_f16<1>,
                             cudaFuncAttributeMaxDynamicSharedMemorySize, GEMM_SMEM);
        cudaFuncSetAttribute((const void*)attn_f16,
                             cudaFuncAttributeMaxDynamicSharedMemorySize, ATTN_SMEM);
        attr_done = true;
    }

    // 0) weight transpose+split (x32)
    {
        dim3 b(32, 8);
        tsplit16_kernel<<<dim3(3 * ND / 32, ND / 32), b>>>(Wqkv, wqh, wql, ND, 3 * ND);
        tsplit16_kernel<<<dim3(ND / 32, ND / 32), b>>>(Wproj, wph, wpl, ND, ND);
    }

    // 1) split x into fp16 hi/lo
    split16_kernel<<<2048, 256>>>(x, axh, axl, NB * NS * ND);

    // 2) QKV GEMM -> split-scatter q/k/v (v transposed)
    gemm_f16<0><<<dim3(3 * ND / 128, NB * NS / 128), 256, GEMM_SMEM>>>(
        axh, axl, wqh, wql, bqkv, nullptr, NB * NS, 3 * ND, ND);

    // 3) fp16 tensor-core causal flash attention -> g_axh/g_axl (pre-split)
    attn_f16<<<dim3(NS / 128, NB * NH), 256, ATTN_SMEM>>>();

    // 4) output projection -> d_out
    gemm_f16<1><<<dim3(ND / 128, NB * NS / 128), 256, GEMM_SMEM>>>(
        axh, axl, wph, wpl, bproj, out, NB * NS, ND, ND);
}

// round 12
// speedup vs baseline: 1.2338x; 1.2338x over previous
#include <cuda_runtime.h>
#include <cuda_fp16.h>
#include <math.h>
#include <stdint.h>

// Problem constants
#define NB  2
#define NS  2048
#define ND  1024
#define NH  16
#define NHD 64
#define SCALE  0.125f    // 1/sqrt(64), applied to scores post-MMA
#define WSCALE 32.0f     // weight pre-scale (keeps w_lo out of fp16 subnormals)
#define INVW   0.03125f

// ---------------------------------------------------------------------------
// Scratch (allocation-free contract: __device__ globals)
// ---------------------------------------------------------------------------
__device__ __half g_qh[NB * NH * NS * NHD];   // [bh][s][hd]  (unscaled, hi only)
__device__ __half g_kh[NB * NH * NS * NHD];   // [bh][s][hd]  hi
__device__ __half g_kl[NB * NH * NS * NHD];   // [bh][s][hd]  lo
__device__ __half g_vh[NB * NH * NS * NHD];   // [bh][hd][s]  (transposed) hi
__device__ __half g_vl[NB * NH * NS * NHD];   // lo
__device__ __half g_axh[NB * NS * ND];        // activations, hi only (x, then attn out)
__device__ __half g_wqh[3 * ND * ND];         // W_qkv^T * 32, hi   [3072 x 1024]
__device__ __half g_wql[3 * ND * ND];
__device__ __half g_wph[ND * ND];             // W_proj^T * 32, hi  [1024 x 1024]
__device__ __half g_wpl[ND * ND];

// ---------------------------------------------------------------------------
// Helpers
// ---------------------------------------------------------------------------
__device__ __forceinline__ uint32_t smem_u32(const void* p) {
    uint32_t a;
    asm("{ .reg .u64 t; cvta.to.shared.u64 t, %1; cvt.u32.u64 %0, t; }"
        : "=r"(a) : "l"(p));
    return a;
}

__device__ __forceinline__ void cp_async16(uint32_t saddr, const void* gptr) {
    asm volatile("cp.async.cg.shared.global [%0], [%1], 16;" :: "r"(saddr), "l"(gptr));
}
#define CP_COMMIT() asm volatile("cp.async.commit_group;" ::: "memory")

__device__ __forceinline__ uint32_t ldh2(const __half* p) {
    return *reinterpret_cast<const uint32_t*>(p);
}

__device__ __forceinline__ uint32_t pack_h2(float a, float b) {
    __half2 h = __floats2half2_rn(a, b);
    return *reinterpret_cast<uint32_t*>(&h);
}

__device__ __forceinline__ void split_h(float v, __half& hi, __half& lo) {
    hi = __float2half_rn(v);
    lo = __float2half_rn(v - __half2float(hi));
}

__device__ __forceinline__ float2 h2f2(uint32_t u) {
    __half2 h = *reinterpret_cast<__half2*>(&u);
    return __half22float2(h);
}

// ldmatrix: 4x (8x8 b16) tiles; per-lane row addresses
__device__ __forceinline__ void ldsm_x4(uint32_t& r0, uint32_t& r1,
                                        uint32_t& r2, uint32_t& r3, uint32_t addr) {
    asm volatile("ldmatrix.sync.aligned.m8n8.x4.shared.b16 {%0,%1,%2,%3}, [%4];"
        : "=r"(r0), "=r"(r1), "=r"(r2), "=r"(r3) : "r"(addr));
}

// m16n8k16 f16 MMA, fp32 accumulate in-place
__device__ __forceinline__ void mma_f16(float* d, const uint32_t* a, const uint32_t* b) {
    asm volatile(
        "mma.sync.aligned.m16n8k16.row.col.f32.f16.f16.f32 "
        "{%0,%1,%2,%3}, {%4,%5,%6,%7}, {%8,%9}, {%0,%1,%2,%3};"
        : "+f"(d[0]), "+f"(d[1]), "+f"(d[2]), "+f"(d[3])
        : "r"(a[0]), "r"(a[1]), "r"(a[2]), "r"(a[3]), "r"(b[0]), "r"(b[1]));
}

// m16n8k16 f16 MMA, fp16 accumulate in-place (for small correction terms)
__device__ __forceinline__ void mma_f16acc(uint32_t* d, const uint32_t* a, const uint32_t* b) {
    asm volatile(
        "mma.sync.aligned.m16n8k16.row.col.f16.f16.f16.f16 "
        "{%0,%1}, {%2,%3,%4,%5}, {%6,%7}, {%0,%1};"
        : "+r"(d[0]), "+r"(d[1])
        : "r"(a[0]), "r"(a[1]), "r"(a[2]), "r"(a[3]), "r"(b[0]), "r"(b[1]));
}

// FFMA-only exp (finite x; clamp handles big negatives). rel err ~2.4e-6.
__device__ __forceinline__ float fexp(float x) {
    x = fmaxf(x, -60.0f);
    const float y = x * 1.44269504f;
    const float t = y + 12582912.0f;              // 1.5 * 2^23
    const int   n = __float_as_int(t) - 0x4B400000;
    const float f = y - (t - 12582912.0f);
    float p = 1.33335581e-3f;
    p = fmaf(p, f, 9.61812910e-3f);
    p = fmaf(p, f, 5.55041087e-2f);
    p = fmaf(p, f, 2.40226510e-1f);
    p = fmaf(p, f, 6.93147182e-1f);
    p = fmaf(p, f, 1.0f);
    return __int_as_float(__float_as_int(p) + (n << 23));
}

// ---------------------------------------------------------------------------
// Prep kernels
// ---------------------------------------------------------------------------
__global__ void convert16_kernel(const float* __restrict__ in,
                                 __half* __restrict__ hi, int n) {
    for (int i = blockIdx.x * blockDim.x + threadIdx.x; i < n; i += gridDim.x * blockDim.x)
        hi[i] = __float2half_rn(in[i]);
}

// W [K,N] row-major -> T [N,K] row-major, scaled by WSCALE, fp16 hi/lo split
__global__ __launch_bounds__(256) void tsplit16_kernel(
    const float* __restrict__ W, __half* __restrict__ Thi, __half* __restrict__ Tlo,
    int K, int N) {
    __shared__ float tile[32][33];
    const int tx = threadIdx.x;
    const int ty = threadIdx.y;
    const int n0 = blockIdx.x * 32;
    const int k0 = blockIdx.y * 32;
#pragma unroll
    for (int i = 0; i < 32; i += 8)
        tile[ty + i][tx] = W[(size_t)(k0 + ty + i) * N + n0 + tx];
    __syncthreads();
#pragma unroll
    for (int i = 0; i < 32; i += 8) {
        float v = tile[tx][ty + i] * WSCALE;
        __half h, l;
        split_h(v, h, l);
        Thi[(size_t)(n0 + ty + i) * K + k0 + tx] = h;
        Tlo[(size_t)(n0 + ty + i) * K + k0 + tx] = l;
    }
}

// ---------------------------------------------------------------------------
// FP16 2-pass mma.sync GEMM: A_hi * (B_hi + B_lo).  A-side lo dropped
// (~1.2e-4 rel).  C[M,N] = (A*B^T)/32.  128x128/CTA, 256 threads,
// warps 2(m) x 4(n), warp tile 64x32, KC 64, double-buffered cp.async.
// Stage tiles: {Ah, Bh, Bl}.  MODE 0: split-scatter QKV;  MODE 1: fp32 C.
// ---------------------------------------------------------------------------
#define KC     64
#define ROWH   72                       // 64 + 8 halves pad
#define TILEH  (128 * ROWH)             // halves per tile
#define STAGEH (3 * TILEH)              // Ah, Bh, Bl
#define GEMM_SMEM (2 * STAGEH * 2)      // bytes = 110592

template <int MODE>
__global__ __launch_bounds__(256, 1) void gemm_f16(
    const __half* __restrict__ Ahi,
    const __half* __restrict__ Bhi, const __half* __restrict__ Blo,
    const float* __restrict__ bias, float* __restrict__ C,
    int M, int N, int K)
{
    extern __shared__ __half smh[];
    const int tid  = threadIdx.x;
    const int lane = tid & 31;
    const int wid  = tid >> 5;
    const int wm   = wid >> 2;
    const int wn   = wid & 3;
    const int g    = lane >> 2;
    const int tg   = lane & 3;
    const int bm = blockIdx.y * 128;
    const int bn = blockIdx.x * 128;

    // ldmatrix per-lane byte offsets (within a 16x16 tile at given base)
    const int la = lane & 7;
    const uint32_t aoff = (uint32_t)(((la + ((lane >> 3) & 1) * 8) * ROWH
                                     + ((lane >> 4) & 1) * 8) * 2);
    const uint32_t boff = (uint32_t)(((la + ((lane >> 4) & 1) * 8) * ROWH
                                     + ((lane >> 3) & 1) * 8) * 2);

    const __half* srcT[3] = {Ahi, Bhi, Blo};

    auto load_stage = [&](int c, int s) {
        const int k0 = c * KC;
        __half* stage = smh + s * STAGEH;
#pragma unroll
        for (int t = 0; t < 3; t++) {
            const __half* src = srcT[t];
            const int rbase = (t == 0) ? bm : bn;
            __half* dst = stage + t * TILEH;
#pragma unroll
            for (int i = 0; i < 4; i++) {
                const int idx = tid + i * 256;     // 0..1023
                const int r = idx >> 3;
                const int q = idx & 7;             // 8 halves (16B) per chunk
                cp_async16(smem_u32(dst + r * ROWH + q * 8),
                           src + (size_t)(rbase + r) * K + k0 + q * 8);
            }
        }
        CP_COMMIT();
    };

    float acc[4][4][4];
    uint32_t acch[4][4][2];              // fp16 accumulator for the B_lo correction
#pragma unroll
    for (int i = 0; i < 4; i++)
#pragma unroll
        for (int j = 0; j < 4; j++) {
#pragma unroll
            for (int kq = 0; kq < 4; kq++) acc[i][j][kq] = 0.f;
            acch[i][j][0] = 0u; acch[i][j][1] = 0u;
        }

    const int NCH = K / KC;
    load_stage(0, 0);

    for (int c = 0; c < NCH; c++) {
        const int s = c & 1;
        if (c + 1 < NCH) {
            load_stage(c + 1, (c + 1) & 1);
            asm volatile("cp.async.wait_group 1;" ::: "memory");
        } else {
            asm volatile("cp.async.wait_group 0;" ::: "memory");
        }
        __syncthreads();

        const uint32_t sA = smem_u32(smh + s * STAGEH);          // Ah (bytes)
        const uint32_t sB = sA + (uint32_t)(TILEH * 2);          // Bh; Bl at +TILEH*2

#pragma unroll
        for (int ks = 0; ks < 4; ks++) {
            const int kb = ks * 16;
            uint32_t ah[4][4], bh[4][2], bl[4][2];
#pragma unroll
            for (int am = 0; am < 4; am++) {
                const uint32_t base = sA + (uint32_t)(((wm * 64 + am * 16) * ROWH + kb) * 2);
                ldsm_x4(ah[am][0], ah[am][1], ah[am][2], ah[am][3], base + aoff);
            }
#pragma unroll
            for (int p = 0; p < 2; p++) {
                const uint32_t base = sB + (uint32_t)(((wn * 32 + p * 16) * ROWH + kb) * 2);
                ldsm_x4(bh[2 * p][0], bh[2 * p][1], bh[2 * p + 1][0], bh[2 * p + 1][1],
                        base + boff);
                ldsm_x4(bl[2 * p][0], bl[2 * p][1], bl[2 * p + 1][0], bl[2 * p + 1][1],
                        base + (uint32_t)(TILEH * 2) + boff);
            }
            // main product: fp32 accumulators
#pragma unroll
            for (int am = 0; am < 4; am++)
#pragma unroll
                for (int an = 0; an < 4; an++)
                    mma_f16(acc[am][an], ah[am], bh[an]);
            // weight-lo correction: fp16 accumulator
#pragma unroll
            for (int am = 0; am < 4; am++)
#pragma unroll
                for (int an = 0; an < 4; an++)
                    mma_f16acc(acch[am][an], ah[am], bl[an]);
        }
        __syncthreads();
    }

    // ---- epilogue: combine fp32 main + fp16 correction ----
#pragma unroll
    for (int am = 0; am < 4; am++) {
        const int row0 = bm + wm * 64 + am * 16 + g;
#pragma unroll
        for (int an = 0; an < 4; an++) {
            const int col = bn + wn * 32 + an * 8 + 2 * tg;
            const float2 c01 = h2f2(acch[am][an][0]);
            const float2 c23 = h2f2(acch[am][an][1]);
            const float v00 = (acc[am][an][0] + c01.x) * INVW + bias[col];
            const float v01 = (acc[am][an][1] + c01.y) * INVW + bias[col + 1];
            const float v10 = (acc[am][an][2] + c23.x) * INVW + bias[col];
            const float v11 = (acc[am][an][3] + c23.y) * INVW + bias[col + 1];
            if (MODE == 0) {
#pragma unroll
                for (int e = 0; e < 4; e++) {
                    const int m = (e < 2) ? row0 : row0 + 8;
                    const int n = col + (e & 1);
                    const float v = (e == 0) ? v00 : (e == 1) ? v01 : (e == 2) ? v10 : v11;
                    const int b = m >> 11;            // NS = 2048
                    const int srow = m & (NS - 1);
                    const int which = n >> 10;        // ND = 1024
                    const int dcol  = n & (ND - 1);
                    const int h  = dcol >> 6;         // NHD = 64
                    const int hd = dcol & 63;
                    const int bhh = b * NH + h;
                    if (which == 0) {
                        const size_t o = ((size_t)bhh * NS + srow) * NHD + hd;
                        g_qh[o] = __float2half_rn(v);
                    } else if (which == 1) {
                        __half hi, lo;
                        split_h(v, hi, lo);
                        const size_t o = ((size_t)bhh * NS + srow) * NHD + hd;
                        g_kh[o] = hi; g_kl[o] = lo;
                    } else {
                        __half hi, lo;
                        split_h(v, hi, lo);
                        const size_t o = ((size_t)bhh * NHD + hd) * NS + srow;
                        g_vh[o] = hi; g_vl[o] = lo;
                    }
                }
            } else {
                *(float2*)(C + (size_t)row0 * N + col)       = make_float2(v00, v01);
                *(float2*)(C + (size_t)(row0 + 8) * N + col) = make_float2(v10, v11);
            }
        }
    }
}

// ---------------------------------------------------------------------------
// FP16 tensor-core causal flash attention.
// Q hi-only; K hi/lo (2-pass QK); V hi/lo (2-pass PV). fp16-acc corrections.
// CTA: 128 q rows, 256 threads = 8 warps (one m16 band each), KV tiles of 64.
// ---------------------------------------------------------------------------
#define AST    72                       // 64 + 8 halves pad
#define TILE_A (64 * AST)               // halves per tile
#define STG_H  (4 * TILE_A)             // Kh, Kl, Vh, Vl
#define ATTN_SMEM (2 * STG_H * 2)       // bytes = 73728

__global__ __launch_bounds__(256, 1) void attn_f16()
{
    extern __shared__ __half smh[];
    const int tid  = threadIdx.x;
    const int lane = tid & 31;
    const int w    = tid >> 5;
    const int g    = lane >> 2;
    const int tg   = lane & 3;
    const int qt   = 15 - blockIdx.x;      // heavy CTAs first
    const int bh   = blockIdx.y;
    const int qbase = qt * 128;

    const int la = lane & 7;
    const uint32_t boff = (uint32_t)(((la + ((lane >> 4) & 1) * 8) * AST
                                     + ((lane >> 3) & 1) * 8) * 2);

    const __half* Qh = g_qh + (size_t)bh * NS * NHD;
    const __half* Kh = g_kh + (size_t)bh * NS * NHD;
    const __half* Kl = g_kl + (size_t)bh * NS * NHD;
    const __half* Vh = g_vh + (size_t)bh * NHD * NS;
    const __half* Vl = g_vl + (size_t)bh * NHD * NS;

    const int r0 = qbase + w * 16 + g;     // global q row of accum row 0

    // Q fragments resident in registers (4 ksteps of k16)
    uint32_t qfh[4][4];
#pragma unroll
    for (int ks = 0; ks < 4; ks++) {
        const int kb = ks * 16;
        qfh[ks][0] = ldh2(Qh + (size_t)r0 * NHD + kb + 2 * tg);
        qfh[ks][1] = ldh2(Qh + (size_t)(r0 + 8) * NHD + kb + 2 * tg);
        qfh[ks][2] = ldh2(Qh + (size_t)r0 * NHD + kb + 8 + 2 * tg);
        qfh[ks][3] = ldh2(Qh + (size_t)(r0 + 8) * NHD + kb + 8 + 2 * tg);
    }

    float o[8][4];
#pragma unroll
    for (int j = 0; j < 8; j++)
#pragma unroll
        for (int c = 0; c < 4; c++) o[j][c] = 0.f;
    float m[2] = {-1e30f, -1e30f};
    float l[2] = {0.f, 0.f};

    const int nt = 2 * qt + 2;

    auto load_tile = [&](int kt, int s) {
        __half* st = smh + s * STG_H;
#pragma unroll
        for (int i = 0; i < 2; i++) {
            const int idx = tid + i * 256;       // 0..511
            const int row = idx >> 3;            // 0..63
            const int q   = idx & 7;             // 8-half chunk
            const uint32_t d = smem_u32(st + row * AST + q * 8);
            cp_async16(d,                  Kh + (size_t)(kt * 64 + row) * NHD + q * 8);
            cp_async16(d + TILE_A * 2,     Kl + (size_t)(kt * 64 + row) * NHD + q * 8);
            cp_async16(d + 2 * TILE_A * 2, Vh + (size_t)row * NS + kt * 64 + q * 8);
            cp_async16(d + 3 * TILE_A * 2, Vl + (size_t)row * NS + kt * 64 + q * 8);
        }
        CP_COMMIT();
    };

    load_tile(0, 0);

    for (int kt = 0; kt < nt; kt++) {
        const int s = kt & 1;
        __syncthreads();                        // all warps done with stage s^1
        if (kt + 1 < nt) {
            load_tile(kt + 1, s ^ 1);
            asm volatile("cp.async.wait_group 1;" ::: "memory");
        } else {
            asm volatile("cp.async.wait_group 0;" ::: "memory");
        }
        __syncthreads();                        // stage s visible to all

        const uint32_t sK = smem_u32(smh + s * STG_H);           // Kh (bytes)
        const uint32_t sV = sK + 2 * TILE_A * 2;                 // Vh

        // ---- S = Q K^T : q_hi*k_hi fp32 acc; q_hi*k_lo fp16 acc ----
        float sc[8][4];
        uint32_t scch[8][2];
#pragma unroll
        for (int j = 0; j < 8; j++) {
#pragma unroll
            for (int c = 0; c < 4; c++) sc[j][c] = 0.f;
            scch[j][0] = 0u; scch[j][1] = 0u;
        }

#pragma unroll
        for (int ks = 0; ks < 4; ks++) {
            const int kb = ks * 16;
            uint32_t bfh[8][2], bfl[8][2];
#pragma unroll
            for (int p = 0; p < 4; p++) {
                const uint32_t base = sK + (uint32_t)((p * 16 * AST + kb) * 2);
                ldsm_x4(bfh[2 * p][0], bfh[2 * p][1], bfh[2 * p + 1][0], bfh[2 * p + 1][1],
                        base + boff);
                ldsm_x4(bfl[2 * p][0], bfl[2 * p][1], bfl[2 * p + 1][0], bfl[2 * p + 1][1],
                        base + (uint32_t)(TILE_A * 2) + boff);
            }
#pragma unroll
            for (int j = 0; j < 8; j++) mma_f16(sc[j], qfh[ks], bfh[j]);
#pragma unroll
            for (int j = 0; j < 8; j++) mma_f16acc(scch[j], qfh[ks], bfl[j]);
        }

        // ---- fold corrections, scale, causal mask ----
#pragma unroll
        for (int j = 0; j < 8; j++) {
            const float2 c01 = h2f2(scch[j][0]);
            const float2 c23 = h2f2(scch[j][1]);
            sc[j][0] = (sc[j][0] + c01.x) * SCALE;
            sc[j][1] = (sc[j][1] + c01.y) * SCALE;
            sc[j][2] = (sc[j][2] + c23.x) * SCALE;
            sc[j][3] = (sc[j][3] + c23.y) * SCALE;
        }
        if (kt >= 2 * qt) {
            const int colb = kt * 64;
#pragma unroll
            for (int j = 0; j < 8; j++) {
                const int c0 = colb + j * 8 + 2 * tg;
#pragma unroll
                for (int c = 0; c < 4; c++) {
                    const int col = c0 + (c & 1);
                    const int row = (c < 2) ? r0 : r0 + 8;
                    if (col > row) sc[j][c] = -1e30f;
                }
            }
        }

        // ---- online softmax (FFMA exp) ----
#pragma unroll
        for (int r = 0; r < 2; r++) {
            float rm = -1e30f;
#pragma unroll
            for (int j = 0; j < 8; j++)
                rm = fmaxf(rm, fmaxf(sc[j][2 * r], sc[j][2 * r + 1]));
            rm = fmaxf(rm, __shfl_xor_sync(0xffffffffu, rm, 1));
            rm = fmaxf(rm, __shfl_xor_sync(0xffffffffu, rm, 2));
            const float mn   = fmaxf(m[r], rm);
            const float corr = fexp(m[r] - mn);
            m[r] = mn;
            float ps = 0.f;
#pragma unroll
            for (int j = 0; j < 8; j++) {
                const float p0 = fexp(sc[j][2 * r]     - mn);
                const float p1 = fexp(sc[j][2 * r + 1] - mn);
                sc[j][2 * r]     = p0;
                sc[j][2 * r + 1] = p1;
                ps += p0 + p1;
            }
            l[r] = l[r] * corr + ps;
#pragma unroll
            for (int j = 0; j < 8; j++) {
                o[j][2 * r]     *= corr;
                o[j][2 * r + 1] *= corr;
            }
        }

        // ---- O += P V : Vh pass fp32 acc; Vl pass per-tile fp16 acc ----
        uint32_t och[8][2];
#pragma unroll
        for (int j = 0; j < 8; j++) { och[j][0] = 0u; och[j][1] = 0u; }
#pragma unroll
        for (int ks = 0; ks < 4; ks++) {
            const int kb = ks * 16;
            uint32_t pa[4];
            pa[0] = pack_h2(sc[2 * ks][0],     sc[2 * ks][1]);
            pa[1] = pack_h2(sc[2 * ks][2],     sc[2 * ks][3]);
            pa[2] = pack_h2(sc[2 * ks + 1][0], sc[2 * ks + 1][1]);
            pa[3] = pack_h2(sc[2 * ks + 1][2], sc[2 * ks + 1][3]);
            uint32_t vfh[8][2], vfl[8][2];
#pragma unroll
            for (int p = 0; p < 4; p++) {
                const uint32_t base = sV + (uint32_t)((p * 16 * AST + kb) * 2);
                ldsm_x4(vfh[2 * p][0], vfh[2 * p][1], vfh[2 * p + 1][0], vfh[2 * p + 1][1],
                        base + boff);
                ldsm_x4(vfl[2 * p][0], vfl[2 * p][1], vfl[2 * p + 1][0], vfl[2 * p + 1][1],
                        base + (uint32_t)(TILE_A * 2) + boff);
            }
#pragma unroll
            for (int j = 0; j < 8; j++) mma_f16(o[j], pa, vfh[j]);
#pragma unroll
            for (int j = 0; j < 8; j++) mma_f16acc(och[j], pa, vfl[j]);
        }
#pragma unroll
        for (int j = 0; j < 8; j++) {
            const float2 c01 = h2f2(och[j][0]);
            const float2 c23 = h2f2(och[j][1]);
            o[j][0] += c01.x; o[j][1] += c01.y;
            o[j][2] += c23.x; o[j][3] += c23.y;
        }
    }

    // ---- finalize: normalize, convert to fp16, write [b,s,d] (hi only) ----
#pragma unroll
    for (int r = 0; r < 2; r++) {
        float lv = l[r];
        lv += __shfl_xor_sync(0xffffffffu, lv, 1);
        lv += __shfl_xor_sync(0xffffffffu, lv, 2);
        l[r] = 1.0f / lv;
    }
    const int b = bh >> 4;
    const int h = bh & (NH - 1);
#pragma unroll
    for (int j = 0; j < 8; j++) {
        const int col = h * NHD + j * 8 + 2 * tg;
#pragma unroll
        for (int r = 0; r < 2; r++) {
            const int row = (r == 0) ? r0 : r0 + 8;
            const size_t off = ((size_t)(b * NS) + row) * ND + col;
            *(uint32_t*)(g_axh + off) = pack_h2(o[j][2 * r] * l[r], o[j][2 * r + 1] * l[r]);
        }
    }
}

// ---------------------------------------------------------------------------
// kernel_launch
// ---------------------------------------------------------------------------
extern "C" void kernel_launch(void* const* d_in, const int* in_sizes, int n_in,
                              void* d_out, int out_size)
{
    (void)in_sizes; (void)n_in; (void)out_size;
    const float* x     = (const float*)d_in[0];
    const float* Wqkv  = (const float*)d_in[1];
    const float* bqkv  = (const float*)d_in[2];
    const float* Wproj = (const float*)d_in[3];
    const float* bproj = (const float*)d_in[4];
    float* out = (float*)d_out;

    void *p_axh, *p_wqh, *p_wql, *p_wph, *p_wpl;
    cudaGetSymbolAddress(&p_axh, g_axh);
    cudaGetSymbolAddress(&p_wqh, g_wqh);
    cudaGetSymbolAddress(&p_wql, g_wql);
    cudaGetSymbolAddress(&p_wph, g_wph);
    cudaGetSymbolAddress(&p_wpl, g_wpl);
    __half* axh = (__half*)p_axh;
    __half* wqh = (__half*)p_wqh; __half* wql = (__half*)p_wql;
    __half* wph = (__half*)p_wph; __half* wpl = (__half*)p_wpl;

    static bool attr_done = false;
    if (!attr_done) {
        cudaFuncSetAttribute((const void*)gemm_f16<0>,
                             cudaFuncAttributeMaxDynamicSharedMemorySize, GEMM_SMEM);
        cudaFuncSetAttribute((const void*)gemm_f16<1>,
                             cudaFuncAttributeMaxDynamicSharedMemorySize, GEMM_SMEM);
        cudaFuncSetAttribute((const void*)attn_f16,
                             cudaFuncAttributeMaxDynamicSharedMemorySize, ATTN_SMEM);
        attr_done = true;
    }

    // 0) weight transpose+split (x32)
    {
        dim3 b(32, 8);
        tsplit16_kernel<<<dim3(3 * ND / 32, ND / 32), b>>>(Wqkv, wqh, wql, ND, 3 * ND);
        tsplit16_kernel<<<dim3(ND / 32, ND / 32), b>>>(Wproj, wph, wpl, ND, ND);
    }

    // 1) convert x to fp16 (hi only; A-side lo correction dropped)
    convert16_kernel<<<2048, 256>>>(x, axh, NB * NS * ND);

    // 2) QKV GEMM -> scatter q (hi) / k,v (hi+lo, v transposed)
    gemm_f16<0><<<dim3(3 * ND / 128, NB * NS / 128), 256, GEMM_SMEM>>>(
        axh, wqh, wql, bqkv, nullptr, NB * NS, 3 * ND, ND);

    // 3) fp16 tensor-core causal flash attention -> g_axh
    attn_f16<<<dim3(NS / 128, NB * NH), 256, ATTN_SMEM>>>();

    // 4) output projection -> d_out
    gemm_f16<1><<<dim3(ND / 128, NB * NS / 128), 256, GEMM_SMEM>>>(
        axh, wph, wpl, bproj, out, NB * NS, ND, ND);
}

// round 13
// speedup vs baseline: 1.3358x; 1.0827x over previous
#include <cuda_runtime.h>
#include <cuda_fp16.h>
#include <math.h>
#include <stdint.h>

// Problem constants
#define NB  2
#define NS  2048
#define ND  1024
#define NH  16
#define NHD 64
#define SCALE  0.125f    // 1/sqrt(64), applied to scores post-MMA
#define WSCALE 32.0f     // weight pre-scale (keeps w_lo out of fp16 subnormals)
#define INVW   0.03125f

// ---------------------------------------------------------------------------
// Scratch (allocation-free contract: __device__ globals)
// ---------------------------------------------------------------------------
__device__ __half g_qh[NB * NH * NS * NHD];   // [bh][s][hd]  (unscaled, hi only)
__device__ __half g_kh[NB * NH * NS * NHD];   // [bh][s][hd]  hi
__device__ __half g_kl[NB * NH * NS * NHD];   // [bh][s][hd]  lo
__device__ __half g_vh[NB * NH * NS * NHD];   // [bh][hd][s]  (transposed, hi only)
__device__ __half g_axh[NB * NS * ND];        // activations, hi only (x, then attn out)
__device__ __half g_wqh[3 * ND * ND];         // W_qkv^T * 32, hi   [3072 x 1024]
__device__ __half g_wql[3 * ND * ND];
__device__ __half g_wph[ND * ND];             // W_proj^T * 32, hi  [1024 x 1024]
__device__ __half g_wpl[ND * ND];

// ---------------------------------------------------------------------------
// Helpers
// ---------------------------------------------------------------------------
__device__ __forceinline__ uint32_t smem_u32(const void* p) {
    uint32_t a;
    asm("{ .reg .u64 t; cvta.to.shared.u64 t, %1; cvt.u32.u64 %0, t; }"
        : "=r"(a) : "l"(p));
    return a;
}

__device__ __forceinline__ void cp_async16(uint32_t saddr, const void* gptr) {
    asm volatile("cp.async.cg.shared.global [%0], [%1], 16;" :: "r"(saddr), "l"(gptr));
}
#define CP_COMMIT() asm volatile("cp.async.commit_group;" ::: "memory")

__device__ __forceinline__ uint32_t ldh2(const __half* p) {
    return *reinterpret_cast<const uint32_t*>(p);
}

__device__ __forceinline__ uint32_t pack_h2(float a, float b) {
    __half2 h = __floats2half2_rn(a, b);
    return *reinterpret_cast<uint32_t*>(&h);
}

__device__ __forceinline__ void split_h(float v, __half& hi, __half& lo) {
    hi = __float2half_rn(v);
    lo = __float2half_rn(v - __half2float(hi));
}

__device__ __forceinline__ float2 h2f2(uint32_t u) {
    __half2 h = *reinterpret_cast<__half2*>(&u);
    return __half22float2(h);
}

// ldmatrix: 4x (8x8 b16) tiles; per-lane row addresses
__device__ __forceinline__ void ldsm_x4(uint32_t& r0, uint32_t& r1,
                                        uint32_t& r2, uint32_t& r3, uint32_t addr) {
    asm volatile("ldmatrix.sync.aligned.m8n8.x4.shared.b16 {%0,%1,%2,%3}, [%4];"
        : "=r"(r0), "=r"(r1), "=r"(r2), "=r"(r3) : "r"(addr));
}

// m16n8k16 f16 MMA, fp32 accumulate in-place
__device__ __forceinline__ void mma_f16(float* d, const uint32_t* a, const uint32_t* b) {
    asm volatile(
        "mma.sync.aligned.m16n8k16.row.col.f32.f16.f16.f32 "
        "{%0,%1,%2,%3}, {%4,%5,%6,%7}, {%8,%9}, {%0,%1,%2,%3};"
        : "+f"(d[0]), "+f"(d[1]), "+f"(d[2]), "+f"(d[3])
        : "r"(a[0]), "r"(a[1]), "r"(a[2]), "r"(a[3]), "r"(b[0]), "r"(b[1]));
}

// m16n8k16 f16 MMA, fp16 accumulate in-place (for small correction terms)
__device__ __forceinline__ void mma_f16acc(uint32_t* d, const uint32_t* a, const uint32_t* b) {
    asm volatile(
        "mma.sync.aligned.m16n8k16.row.col.f16.f16.f16.f16 "
        "{%0,%1}, {%2,%3,%4,%5}, {%6,%7}, {%0,%1};"
        : "+r"(d[0]), "+r"(d[1])
        : "r"(a[0]), "r"(a[1]), "r"(a[2]), "r"(a[3]), "r"(b[0]), "r"(b[1]));
}

// FFMA-only exp (finite x; clamp handles big negatives). rel err ~2.4e-6.
__device__ __forceinline__ float fexp(float x) {
    x = fmaxf(x, -60.0f);
    const float y = x * 1.44269504f;
    const float t = y + 12582912.0f;              // 1.5 * 2^23
    const int   n = __float_as_int(t) - 0x4B400000;
    const float f = y - (t - 12582912.0f);
    float p = 1.33335581e-3f;
    p = fmaf(p, f, 9.61812910e-3f);
    p = fmaf(p, f, 5.55041087e-2f);
    p = fmaf(p, f, 2.40226510e-1f);
    p = fmaf(p, f, 6.93147182e-1f);
    p = fmaf(p, f, 1.0f);
    return __int_as_float(__float_as_int(p) + (n << 23));
}

// ---------------------------------------------------------------------------
// Prep kernels
// ---------------------------------------------------------------------------
__global__ void convert16_kernel(const float* __restrict__ in,
                                 __half* __restrict__ hi, int n) {
    for (int i = blockIdx.x * blockDim.x + threadIdx.x; i < n; i += gridDim.x * blockDim.x)
        hi[i] = __float2half_rn(in[i]);
}

// W [K,N] row-major -> T [N,K] row-major, scaled by WSCALE, fp16 hi/lo split
__global__ __launch_bounds__(256) void tsplit16_kernel(
    const float* __restrict__ W, __half* __restrict__ Thi, __half* __restrict__ Tlo,
    int K, int N) {
    __shared__ float tile[32][33];
    const int tx = threadIdx.x;
    const int ty = threadIdx.y;
    const int n0 = blockIdx.x * 32;
    const int k0 = blockIdx.y * 32;
#pragma unroll
    for (int i = 0; i < 32; i += 8)
        tile[ty + i][tx] = W[(size_t)(k0 + ty + i) * N + n0 + tx];
    __syncthreads();
#pragma unroll
    for (int i = 0; i < 32; i += 8) {
        float v = tile[tx][ty + i] * WSCALE;
        __half h, l;
        split_h(v, h, l);
        Thi[(size_t)(n0 + ty + i) * K + k0 + tx] = h;
        Tlo[(size_t)(n0 + ty + i) * K + k0 + tx] = l;
    }
}

// ---------------------------------------------------------------------------
// FP16 2-pass mma.sync GEMM: A_hi * (B_hi + B_lo).  128x128/CTA, 256 threads,
// warps 2(m) x 4(n), warp tile 64x32, KC 64, double-buffered cp.async.
// Stage tiles: {Ah, Bh, Bl}.  MODE 0: scatter QKV;  MODE 1: fp32 C.
// ---------------------------------------------------------------------------
#define KC     64
#define ROWH   72                       // 64 + 8 halves pad
#define TILEH  (128 * ROWH)             // halves per tile
#define STAGEH (3 * TILEH)              // Ah, Bh, Bl
#define GEMM_SMEM (2 * STAGEH * 2)      // bytes = 110592

template <int MODE>
__global__ __launch_bounds__(256, 1) void gemm_f16(
    const __half* __restrict__ Ahi,
    const __half* __restrict__ Bhi, const __half* __restrict__ Blo,
    const float* __restrict__ bias, float* __restrict__ C,
    int M, int N, int K)
{
    extern __shared__ __half smh[];
    const int tid  = threadIdx.x;
    const int lane = tid & 31;
    const int wid  = tid >> 5;
    const int wm   = wid >> 2;
    const int wn   = wid & 3;
    const int g    = lane >> 2;
    const int tg   = lane & 3;
    const int bm = blockIdx.y * 128;
    const int bn = blockIdx.x * 128;

    // ldmatrix per-lane byte offsets (within a 16x16 tile at given base)
    const int la = lane & 7;
    const uint32_t aoff = (uint32_t)(((la + ((lane >> 3) & 1) * 8) * ROWH
                                     + ((lane >> 4) & 1) * 8) * 2);
    const uint32_t boff = (uint32_t)(((la + ((lane >> 4) & 1) * 8) * ROWH
                                     + ((lane >> 3) & 1) * 8) * 2);

    const __half* srcT[3] = {Ahi, Bhi, Blo};

    auto load_stage = [&](int c, int s) {
        const int k0 = c * KC;
        __half* stage = smh + s * STAGEH;
#pragma unroll
        for (int t = 0; t < 3; t++) {
            const __half* src = srcT[t];
            const int rbase = (t == 0) ? bm : bn;
            __half* dst = stage + t * TILEH;
#pragma unroll
            for (int i = 0; i < 4; i++) {
                const int idx = tid + i * 256;     // 0..1023
                const int r = idx >> 3;
                const int q = idx & 7;             // 8 halves (16B) per chunk
                cp_async16(smem_u32(dst + r * ROWH + q * 8),
                           src + (size_t)(rbase + r) * K + k0 + q * 8);
            }
        }
        CP_COMMIT();
    };

    float acc[4][4][4];
    uint32_t acch[4][4][2];              // fp16 accumulator for the B_lo correction
#pragma unroll
    for (int i = 0; i < 4; i++)
#pragma unroll
        for (int j = 0; j < 4; j++) {
#pragma unroll
            for (int kq = 0; kq < 4; kq++) acc[i][j][kq] = 0.f;
            acch[i][j][0] = 0u; acch[i][j][1] = 0u;
        }

    const int NCH = K / KC;
    load_stage(0, 0);

    for (int c = 0; c < NCH; c++) {
        const int s = c & 1;
        if (c + 1 < NCH) {
            load_stage(c + 1, (c + 1) & 1);
            asm volatile("cp.async.wait_group 1;" ::: "memory");
        } else {
            asm volatile("cp.async.wait_group 0;" ::: "memory");
        }
        __syncthreads();

        const uint32_t sA = smem_u32(smh + s * STAGEH);          // Ah (bytes)
        const uint32_t sB = sA + (uint32_t)(TILEH * 2);          // Bh; Bl at +TILEH*2

#pragma unroll
        for (int ks = 0; ks < 4; ks++) {
            const int kb = ks * 16;
            uint32_t ah[4][4], bh[4][2], bl[4][2];
#pragma unroll
            for (int am = 0; am < 4; am++) {
                const uint32_t base = sA + (uint32_t)(((wm * 64 + am * 16) * ROWH + kb) * 2);
                ldsm_x4(ah[am][0], ah[am][1], ah[am][2], ah[am][3], base + aoff);
            }
#pragma unroll
            for (int p = 0; p < 2; p++) {
                const uint32_t base = sB + (uint32_t)(((wn * 32 + p * 16) * ROWH + kb) * 2);
                ldsm_x4(bh[2 * p][0], bh[2 * p][1], bh[2 * p + 1][0], bh[2 * p + 1][1],
                        base + boff);
                ldsm_x4(bl[2 * p][0], bl[2 * p][1], bl[2 * p + 1][0], bl[2 * p + 1][1],
                        base + (uint32_t)(TILEH * 2) + boff);
            }
            // main product: fp32 accumulators
#pragma unroll
            for (int am = 0; am < 4; am++)
#pragma unroll
                for (int an = 0; an < 4; an++)
                    mma_f16(acc[am][an], ah[am], bh[an]);
            // weight-lo correction: fp16 accumulator
#pragma unroll
            for (int am = 0; am < 4; am++)
#pragma unroll
                for (int an = 0; an < 4; an++)
                    mma_f16acc(acch[am][an], ah[am], bl[an]);
        }
        __syncthreads();
    }

    // ---- epilogue: combine fp32 main + fp16 correction ----
#pragma unroll
    for (int am = 0; am < 4; am++) {
        const int row0 = bm + wm * 64 + am * 16 + g;
#pragma unroll
        for (int an = 0; an < 4; an++) {
            const int col = bn + wn * 32 + an * 8 + 2 * tg;
            const float2 c01 = h2f2(acch[am][an][0]);
            const float2 c23 = h2f2(acch[am][an][1]);
            const float v00 = (acc[am][an][0] + c01.x) * INVW + bias[col];
            const float v01 = (acc[am][an][1] + c01.y) * INVW + bias[col + 1];
            const float v10 = (acc[am][an][2] + c23.x) * INVW + bias[col];
            const float v11 = (acc[am][an][3] + c23.y) * INVW + bias[col + 1];
            if (MODE == 0) {
#pragma unroll
                for (int e = 0; e < 4; e++) {
                    const int m = (e < 2) ? row0 : row0 + 8;
                    const int n = col + (e & 1);
                    const float v = (e == 0) ? v00 : (e == 1) ? v01 : (e == 2) ? v10 : v11;
                    const int b = m >> 11;            // NS = 2048
                    const int srow = m & (NS - 1);
                    const int which = n >> 10;        // ND = 1024
                    const int dcol  = n & (ND - 1);
                    const int h  = dcol >> 6;         // NHD = 64
                    const int hd = dcol & 63;
                    const int bhh = b * NH + h;
                    if (which == 0) {
                        const size_t o = ((size_t)bhh * NS + srow) * NHD + hd;
                        g_qh[o] = __float2half_rn(v);
                    } else if (which == 1) {
                        __half hi, lo;
                        split_h(v, hi, lo);
                        const size_t o = ((size_t)bhh * NS + srow) * NHD + hd;
                        g_kh[o] = hi; g_kl[o] = lo;
                    } else {
                        const size_t o = ((size_t)bhh * NHD + hd) * NS + srow;
                        g_vh[o] = __float2half_rn(v);
                    }
                }
            } else {
                *(float2*)(C + (size_t)row0 * N + col)       = make_float2(v00, v01);
                *(float2*)(C + (size_t)(row0 + 8) * N + col) = make_float2(v10, v11);
            }
        }
    }
}

// ---------------------------------------------------------------------------
// FP16 tensor-core causal flash attention.
// Q hi-only; K hi/lo (2-pass QK); V hi-only (1-pass PV).
// 128-row KV stages processed as two 64-col sub-tiles (half the sync count).
// CTA: 128 q rows, 256 threads = 8 warps (one m16 band each).
// ---------------------------------------------------------------------------
#define KST    72                        // K tile stride: 64 hd + 8 pad
#define VST    136                       // V tile stride: 128 kv + 8 pad
#define KTILE  (128 * KST)               // 9216 halves (128 kv rows x 64 hd)
#define VTILE  (64 * VST)                // 8704 halves (64 hd rows x 128 kv)
#define STG_H  (2 * KTILE + VTILE)       // Kh, Kl, Vh = 27136 halves
#define ATTN_SMEM (2 * STG_H * 2)        // bytes = 108544

__global__ __launch_bounds__(256, 1) void attn_f16()
{
    extern __shared__ __half smh[];
    const int tid  = threadIdx.x;
    const int lane = tid & 31;
    const int w    = tid >> 5;
    const int g    = lane >> 2;
    const int tg   = lane & 3;
    const int qt   = 15 - blockIdx.x;      // heavy CTAs first
    const int bh   = blockIdx.y;
    const int qbase = qt * 128;

    const int la = lane & 7;
    const uint32_t boffK = (uint32_t)(((la + ((lane >> 4) & 1) * 8) * KST
                                      + ((lane >> 3) & 1) * 8) * 2);
    const uint32_t boffV = (uint32_t)(((la + ((lane >> 4) & 1) * 8) * VST
                                      + ((lane >> 3) & 1) * 8) * 2);

    const __half* Qh = g_qh + (size_t)bh * NS * NHD;
    const __half* Kh = g_kh + (size_t)bh * NS * NHD;
    const __half* Kl = g_kl + (size_t)bh * NS * NHD;
    const __half* Vh = g_vh + (size_t)bh * NHD * NS;

    const int r0 = qbase + w * 16 + g;     // global q row of accum row 0

    // Q fragments resident in registers (4 ksteps of k16)
    uint32_t qfh[4][4];
#pragma unroll
    for (int ks = 0; ks < 4; ks++) {
        const int kb = ks * 16;
        qfh[ks][0] = ldh2(Qh + (size_t)r0 * NHD + kb + 2 * tg);
        qfh[ks][1] = ldh2(Qh + (size_t)(r0 + 8) * NHD + kb + 2 * tg);
        qfh[ks][2] = ldh2(Qh + (size_t)r0 * NHD + kb + 8 + 2 * tg);
        qfh[ks][3] = ldh2(Qh + (size_t)(r0 + 8) * NHD + kb + 8 + 2 * tg);
    }

    float o[8][4];
#pragma unroll
    for (int j = 0; j < 8; j++)
#pragma unroll
        for (int c = 0; c < 4; c++) o[j][c] = 0.f;
    float m[2] = {-1e30f, -1e30f};
    float l[2] = {0.f, 0.f};

    const int nt = qt + 1;                  // 128-row KV stages

    auto load_tile = [&](int kt, int s) {
        __half* st = smh + s * STG_H;
        // Kh, Kl: 128 kv rows x 64 halves
#pragma unroll
        for (int i = 0; i < 4; i++) {
            const int idx = tid + i * 256;       // 0..1023
            const int row = idx >> 3;            // 0..127
            const int q   = idx & 7;
            const uint32_t d = smem_u32(st + row * KST + q * 8);
            cp_async16(d,             Kh + (size_t)(kt * 128 + row) * NHD + q * 8);
            cp_async16(d + KTILE * 2, Kl + (size_t)(kt * 128 + row) * NHD + q * 8);
        }
        // Vh: 64 hd rows x 128 halves
#pragma unroll
        for (int i = 0; i < 4; i++) {
            const int idx = tid + i * 256;       // 0..1023
            const int row = idx >> 4;            // 0..63
            const int q   = idx & 15;
            cp_async16(smem_u32(st + 2 * KTILE + row * VST + q * 8),
                       Vh + (size_t)row * NS + kt * 128 + q * 8);
        }
        CP_COMMIT();
    };

    load_tile(0, 0);

    for (int kt = 0; kt < nt; kt++) {
        const int s = kt & 1;
        __syncthreads();                        // all warps done with stage s^1
        if (kt + 1 < nt) {
            load_tile(kt + 1, s ^ 1);
            asm volatile("cp.async.wait_group 1;" ::: "memory");
        } else {
            asm volatile("cp.async.wait_group 0;" ::: "memory");
        }
        __syncthreads();                        // stage s visible to all

        const uint32_t sK = smem_u32(smh + s * STG_H);           // Kh (bytes)
        const uint32_t sV = sK + (uint32_t)(2 * KTILE * 2);      // Vh

#pragma unroll
        for (int st2 = 0; st2 < 2; st2++) {
            // On the diagonal stage, warps 0..3 have every column of sub-tile 1
            // masked (cols >= qbase+64 > all their rows) — skip entirely.
            if (kt == nt - 1 && st2 == 1 && w < 4) continue;
            const int colbase = kt * 128 + st2 * 64;

            // ---- S = Q K^T : q_hi*k_hi fp32 acc; q_hi*k_lo fp16 acc ----
            float sc[8][4];
            uint32_t scch[8][2];
#pragma unroll
            for (int j = 0; j < 8; j++) {
#pragma unroll
                for (int c = 0; c < 4; c++) sc[j][c] = 0.f;
                scch[j][0] = 0u; scch[j][1] = 0u;
            }

#pragma unroll
            for (int ks = 0; ks < 4; ks++) {
                const int kb = ks * 16;
                uint32_t bfh[8][2], bfl[8][2];
#pragma unroll
                for (int p = 0; p < 4; p++) {
                    const uint32_t base = sK
                        + (uint32_t)((((st2 * 64 + p * 16) * KST) + kb) * 2);
                    ldsm_x4(bfh[2 * p][0], bfh[2 * p][1],
                            bfh[2 * p + 1][0], bfh[2 * p + 1][1], base + boffK);
                    ldsm_x4(bfl[2 * p][0], bfl[2 * p][1],
                            bfl[2 * p + 1][0], bfl[2 * p + 1][1],
                            base + (uint32_t)(KTILE * 2) + boffK);
                }
#pragma unroll
                for (int j = 0; j < 8; j++) mma_f16(sc[j], qfh[ks], bfh[j]);
#pragma unroll
                for (int j = 0; j < 8; j++) mma_f16acc(scch[j], qfh[ks], bfl[j]);
            }

            // ---- fold corrections, scale, causal mask ----
#pragma unroll
            for (int j = 0; j < 8; j++) {
                const float2 c01 = h2f2(scch[j][0]);
                const float2 c23 = h2f2(scch[j][1]);
                sc[j][0] = (sc[j][0] + c01.x) * SCALE;
                sc[j][1] = (sc[j][1] + c01.y) * SCALE;
                sc[j][2] = (sc[j][2] + c23.x) * SCALE;
                sc[j][3] = (sc[j][3] + c23.y) * SCALE;
            }
            if (kt == nt - 1) {
#pragma unroll
                for (int j = 0; j < 8; j++) {
                    const int c0 = colbase + j * 8 + 2 * tg;
#pragma unroll
                    for (int c = 0; c < 4; c++) {
                        const int col = c0 + (c & 1);
                        const int row = (c < 2) ? r0 : r0 + 8;
                        if (col > row) sc[j][c] = -1e30f;
                    }
                }
            }

            // ---- online softmax (FFMA exp) ----
#pragma unroll
            for (int r = 0; r < 2; r++) {
                float rm = -1e30f;
#pragma unroll
                for (int j = 0; j < 8; j++)
                    rm = fmaxf(rm, fmaxf(sc[j][2 * r], sc[j][2 * r + 1]));
                rm = fmaxf(rm, __shfl_xor_sync(0xffffffffu, rm, 1));
                rm = fmaxf(rm, __shfl_xor_sync(0xffffffffu, rm, 2));
                const float mn   = fmaxf(m[r], rm);
                const float corr = fexp(m[r] - mn);
                m[r] = mn;
                float ps = 0.f;
#pragma unroll
                for (int j = 0; j < 8; j++) {
                    const float p0 = fexp(sc[j][2 * r]     - mn);
                    const float p1 = fexp(sc[j][2 * r + 1] - mn);
                    sc[j][2 * r]     = p0;
                    sc[j][2 * r + 1] = p1;
                    ps += p0 + p1;
                }
                l[r] = l[r] * corr + ps;
#pragma unroll
                for (int j = 0; j < 8; j++) {
                    o[j][2 * r]     *= corr;
                    o[j][2 * r + 1] *= corr;
                }
            }

            // ---- O += P V  (single fp32 pass; V_lo dropped) ----
#pragma unroll
            for (int ks = 0; ks < 4; ks++) {
                const int kb = ks * 16;
                uint32_t pa[4];
                pa[0] = pack_h2(sc[2 * ks][0],     sc[2 * ks][1]);
                pa[1] = pack_h2(sc[2 * ks][2],     sc[2 * ks][3]);
                pa[2] = pack_h2(sc[2 * ks + 1][0], sc[2 * ks + 1][1]);
                pa[3] = pack_h2(sc[2 * ks + 1][2], sc[2 * ks + 1][3]);
                uint32_t vfh[8][2];
#pragma unroll
                for (int p = 0; p < 4; p++) {
                    const uint32_t base = sV
                        + (uint32_t)(((p * 16) * VST + st2 * 64 + kb) * 2);
                    ldsm_x4(vfh[2 * p][0], vfh[2 * p][1],
                            vfh[2 * p + 1][0], vfh[2 * p + 1][1], base + boffV);
                }
#pragma unroll
                for (int j = 0; j < 8; j++) mma_f16(o[j], pa, vfh[j]);
            }
        }
    }

    // ---- finalize: normalize, convert to fp16, write [b,s,d] (hi only) ----
#pragma unroll
    for (int r = 0; r < 2; r++) {
        float lv = l[r];
        lv += __shfl_xor_sync(0xffffffffu, lv, 1);
        lv += __shfl_xor_sync(0xffffffffu, lv, 2);
        l[r] = 1.0f / lv;
    }
    const int b = bh >> 4;
    const int h = bh & (NH - 1);
#pragma unroll
    for (int j = 0; j < 8; j++) {
        const int col = h * NHD + j * 8 + 2 * tg;
#pragma unroll
        for (int r = 0; r < 2; r++) {
            const int row = (r == 0) ? r0 : r0 + 8;
            const size_t off = ((size_t)(b * NS) + row) * ND + col;
            *(uint32_t*)(g_axh + off) = pack_h2(o[j][2 * r] * l[r], o[j][2 * r + 1] * l[r]);
        }
    }
}

// ---------------------------------------------------------------------------
// kernel_launch
// ---------------------------------------------------------------------------
extern "C" void kernel_launch(void* const* d_in, const int* in_sizes, int n_in,
                              void* d_out, int out_size)
{
    (void)in_sizes; (void)n_in; (void)out_size;
    const float* x     = (const float*)d_in[0];
    const float* Wqkv  = (const float*)d_in[1];
    const float* bqkv  = (const float*)d_in[2];
    const float* Wproj = (const float*)d_in[3];
    const float* bproj = (const float*)d_in[4];
    float* out = (float*)d_out;

    void *p_axh, *p_wqh, *p_wql, *p_wph, *p_wpl;
    cudaGetSymbolAddress(&p_axh, g_axh);
    cudaGetSymbolAddress(&p_wqh, g_wqh);
    cudaGetSymbolAddress(&p_wql, g_wql);
    cudaGetSymbolAddress(&p_wph, g_wph);
    cudaGetSymbolAddress(&p_wpl, g_wpl);
    __half* axh = (__half*)p_axh;
    __half* wqh = (__half*)p_wqh; __half* wql = (__half*)p_wql;
    __half* wph = (__half*)p_wph; __half* wpl = (__half*)p_wpl;

    static bool attr_done = false;
    if (!attr_done) {
        cudaFuncSetAttribute((const void*)gemm_f16<0>,
                             cudaFuncAttributeMaxDynamicSharedMemorySize, GEMM_SMEM);
        cudaFuncSetAttribute((const void*)gemm_f16<1>,
                             cudaFuncAttributeMaxDynamicSharedMemorySize, GEMM_SMEM);
        cudaFuncSetAttribute((const void*)attn_f16,
                             cudaFuncAttributeMaxDynamicSharedMemorySize, ATTN_SMEM);
        attr_done = true;
    }

    // 0) weight transpose+split (x32)
    {
        dim3 b(32, 8);
        tsplit16_kernel<<<dim3(3 * ND / 32, ND / 32), b>>>(Wqkv, wqh, wql, ND, 3 * ND);
        tsplit16_kernel<<<dim3(ND / 32, ND / 32), b>>>(Wproj, wph, wpl, ND, ND);
    }

    // 1) convert x to fp16 (hi only)
    convert16_kernel<<<2048, 256>>>(x, axh, NB * NS * ND);

    // 2) QKV GEMM -> scatter q (hi) / k (hi+lo) / v (hi, transposed)
    gemm_f16<0><<<dim3(3 * ND / 128, NB * NS / 128), 256, GEMM_SMEM>>>(
        axh, wqh, wql, bqkv, nullptr, NB * NS, 3 * ND, ND);

    // 3) fp16 tensor-core causal flash attention -> g_axh
    attn_f16<<<dim3(NS / 128, NB * NH), 256, ATTN_SMEM>>>();

    // 4) output projection -> d_out
    gemm_f16<1><<<dim3(ND / 128, NB * NS / 128), 256, GEMM_SMEM>>>(
        axh, wph, wpl, bproj, out, NB * NS, ND, ND);
}

// round 14
// speedup vs baseline: 1.6724x; 1.2519x over previous
#include <cuda_runtime.h>
#include <cuda_fp16.h>
#include <math.h>
#include <stdint.h>

// Problem constants
#define NB  2
#define NS  2048
#define ND  1024
#define NH  16
#define NHD 64
#define SCALE  0.125f    // 1/sqrt(64), applied to scores post-MMA

// ---------------------------------------------------------------------------
// Scratch (allocation-free contract: __device__ globals)
// ---------------------------------------------------------------------------
__device__ __half g_qh[NB * NH * NS * NHD];   // [bh][s][hd]  (unscaled, hi only)
__device__ __half g_kh[NB * NH * NS * NHD];   // [bh][s][hd]  hi
__device__ __half g_kl[NB * NH * NS * NHD];   // [bh][s][hd]  lo
__device__ __half g_vh[NB * NH * NS * NHD];   // [bh][hd][s]  (transposed, hi only)
__device__ __half g_axh[NB * NS * ND];        // activations, hi only (x, then attn out)
__device__ __half g_wqh[3 * ND * ND];         // W_qkv^T fp16  [3072 x 1024]
__device__ __half g_wph[ND * ND];             // W_proj^T fp16 [1024 x 1024]

// ---------------------------------------------------------------------------
// Helpers
// ---------------------------------------------------------------------------
__device__ __forceinline__ uint32_t smem_u32(const void* p) {
    uint32_t a;
    asm("{ .reg .u64 t; cvta.to.shared.u64 t, %1; cvt.u32.u64 %0, t; }"
        : "=r"(a) : "l"(p));
    return a;
}

__device__ __forceinline__ void cp_async16(uint32_t saddr, const void* gptr) {
    asm volatile("cp.async.cg.shared.global [%0], [%1], 16;" :: "r"(saddr), "l"(gptr));
}
#define CP_COMMIT() asm volatile("cp.async.commit_group;" ::: "memory")

__device__ __forceinline__ uint32_t ldh2(const __half* p) {
    return *reinterpret_cast<const uint32_t*>(p);
}

__device__ __forceinline__ uint32_t pack_h2(float a, float b) {
    __half2 h = __floats2half2_rn(a, b);
    return *reinterpret_cast<uint32_t*>(&h);
}

__device__ __forceinline__ void split_h(float v, __half& hi, __half& lo) {
    hi = __float2half_rn(v);
    lo = __float2half_rn(v - __half2float(hi));
}

__device__ __forceinline__ float2 h2f2(uint32_t u) {
    __half2 h = *reinterpret_cast<__half2*>(&u);
    return __half22float2(h);
}

// ldmatrix: 4x (8x8 b16) tiles; per-lane row addresses
__device__ __forceinline__ void ldsm_x4(uint32_t& r0, uint32_t& r1,
                                        uint32_t& r2, uint32_t& r3, uint32_t addr) {
    asm volatile("ldmatrix.sync.aligned.m8n8.x4.shared.b16 {%0,%1,%2,%3}, [%4];"
        : "=r"(r0), "=r"(r1), "=r"(r2), "=r"(r3) : "r"(addr));
}

// m16n8k16 f16 MMA, fp32 accumulate in-place
__device__ __forceinline__ void mma_f16(float* d, const uint32_t* a, const uint32_t* b) {
    asm volatile(
        "mma.sync.aligned.m16n8k16.row.col.f32.f16.f16.f32 "
        "{%0,%1,%2,%3}, {%4,%5,%6,%7}, {%8,%9}, {%0,%1,%2,%3};"
        : "+f"(d[0]), "+f"(d[1]), "+f"(d[2]), "+f"(d[3])
        : "r"(a[0]), "r"(a[1]), "r"(a[2]), "r"(a[3]), "r"(b[0]), "r"(b[1]));
}

// m16n8k16 f16 MMA, fp16 accumulate in-place (attention K_lo correction)
__device__ __forceinline__ void mma_f16acc(uint32_t* d, const uint32_t* a, const uint32_t* b) {
    asm volatile(
        "mma.sync.aligned.m16n8k16.row.col.f16.f16.f16.f16 "
        "{%0,%1}, {%2,%3,%4,%5}, {%6,%7}, {%0,%1};"
        : "+r"(d[0]), "+r"(d[1])
        : "r"(a[0]), "r"(a[1]), "r"(a[2]), "r"(a[3]), "r"(b[0]), "r"(b[1]));
}

// FFMA-only exp (finite x; clamp handles big negatives). rel err ~2.4e-6.
__device__ __forceinline__ float fexp(float x) {
    x = fmaxf(x, -60.0f);
    const float y = x * 1.44269504f;
    const float t = y + 12582912.0f;              // 1.5 * 2^23
    const int   n = __float_as_int(t) - 0x4B400000;
    const float f = y - (t - 12582912.0f);
    float p = 1.33335581e-3f;
    p = fmaf(p, f, 9.61812910e-3f);
    p = fmaf(p, f, 5.55041087e-2f);
    p = fmaf(p, f, 2.40226510e-1f);
    p = fmaf(p, f, 6.93147182e-1f);
    p = fmaf(p, f, 1.0f);
    return __int_as_float(__float_as_int(p) + (n << 23));
}

// ---------------------------------------------------------------------------
// Prep kernels
// ---------------------------------------------------------------------------
__global__ void convert16_kernel(const float* __restrict__ in,
                                 __half* __restrict__ hi, int n) {
    for (int i = blockIdx.x * blockDim.x + threadIdx.x; i < n; i += gridDim.x * blockDim.x)
        hi[i] = __float2half_rn(in[i]);
}

// W [K,N] row-major -> T [N,K] row-major, fp16 (hi only)
__global__ __launch_bounds__(256) void tconv16_kernel(
    const float* __restrict__ W, __half* __restrict__ Thi, int K, int N) {
    __shared__ float tile[32][33];
    const int tx = threadIdx.x;
    const int ty = threadIdx.y;
    const int n0 = blockIdx.x * 32;
    const int k0 = blockIdx.y * 32;
#pragma unroll
    for (int i = 0; i < 32; i += 8)
        tile[ty + i][tx] = W[(size_t)(k0 + ty + i) * N + n0 + tx];
    __syncthreads();
#pragma unroll
    for (int i = 0; i < 32; i += 8)
        Thi[(size_t)(n0 + ty + i) * K + k0 + tx] = __float2half_rn(tile[tx][ty + i]);
}

// ---------------------------------------------------------------------------
// Pure FP16 mma.sync GEMM (single pass, fp32 acc): C = A_hi * B_hi^T + bias.
// 128x128/CTA, 256 threads, warps 2(m) x 4(n), warp tile 64x32, KC 64,
// double-buffered cp.async.  Stage tiles: {Ah, Bh}.
// MODE 0: scatter QKV (q hi; k hi+lo; v hi transposed);  MODE 1: fp32 C.
// ---------------------------------------------------------------------------
#define KC     64
#define ROWH   72                       // 64 + 8 halves pad
#define TILEH  (128 * ROWH)             // halves per tile
#define STAGEH (2 * TILEH)              // Ah, Bh
#define GEMM_SMEM (2 * STAGEH * 2)      // bytes = 73728

template <int MODE>
__global__ __launch_bounds__(256, 1) void gemm_f16(
    const __half* __restrict__ Ahi, const __half* __restrict__ Bhi,
    const float* __restrict__ bias, float* __restrict__ C,
    int M, int N, int K)
{
    extern __shared__ __half smh[];
    const int tid  = threadIdx.x;
    const int lane = tid & 31;
    const int wid  = tid >> 5;
    const int wm   = wid >> 2;
    const int wn   = wid & 3;
    const int g    = lane >> 2;
    const int tg   = lane & 3;
    const int bm = blockIdx.y * 128;
    const int bn = blockIdx.x * 128;

    // ldmatrix per-lane byte offsets (within a 16x16 tile at given base)
    const int la = lane & 7;
    const uint32_t aoff = (uint32_t)(((la + ((lane >> 3) & 1) * 8) * ROWH
                                     + ((lane >> 4) & 1) * 8) * 2);
    const uint32_t boff = (uint32_t)(((la + ((lane >> 4) & 1) * 8) * ROWH
                                     + ((lane >> 3) & 1) * 8) * 2);

    auto load_stage = [&](int c, int s) {
        const int k0 = c * KC;
        __half* stage = smh + s * STAGEH;
#pragma unroll
        for (int t = 0; t < 2; t++) {
            const __half* src = (t == 0) ? Ahi : Bhi;
            const int rbase = (t == 0) ? bm : bn;
            __half* dst = stage + t * TILEH;
#pragma unroll
            for (int i = 0; i < 4; i++) {
                const int idx = tid + i * 256;     // 0..1023
                const int r = idx >> 3;
                const int q = idx & 7;             // 8 halves (16B) per chunk
                cp_async16(smem_u32(dst + r * ROWH + q * 8),
                           src + (size_t)(rbase + r) * K + k0 + q * 8);
            }
        }
        CP_COMMIT();
    };

    float acc[4][4][4];
#pragma unroll
    for (int i = 0; i < 4; i++)
#pragma unroll
        for (int j = 0; j < 4; j++)
#pragma unroll
            for (int kq = 0; kq < 4; kq++) acc[i][j][kq] = 0.f;

    const int NCH = K / KC;
    load_stage(0, 0);

    for (int c = 0; c < NCH; c++) {
        const int s = c & 1;
        if (c + 1 < NCH) {
            load_stage(c + 1, (c + 1) & 1);
            asm volatile("cp.async.wait_group 1;" ::: "memory");
        } else {
            asm volatile("cp.async.wait_group 0;" ::: "memory");
        }
        __syncthreads();

        const uint32_t sA = smem_u32(smh + s * STAGEH);          // Ah (bytes)
        const uint32_t sB = sA + (uint32_t)(TILEH * 2);          // Bh

#pragma unroll
        for (int ks = 0; ks < 4; ks++) {
            const int kb = ks * 16;
            uint32_t ah[4][4], bh[4][2];
#pragma unroll
            for (int am = 0; am < 4; am++) {
                const uint32_t base = sA + (uint32_t)(((wm * 64 + am * 16) * ROWH + kb) * 2);
                ldsm_x4(ah[am][0], ah[am][1], ah[am][2], ah[am][3], base + aoff);
            }
#pragma unroll
            for (int p = 0; p < 2; p++) {
                const uint32_t base = sB + (uint32_t)(((wn * 32 + p * 16) * ROWH + kb) * 2);
                ldsm_x4(bh[2 * p][0], bh[2 * p][1], bh[2 * p + 1][0], bh[2 * p + 1][1],
                        base + boff);
            }
#pragma unroll
            for (int am = 0; am < 4; am++)
#pragma unroll
                for (int an = 0; an < 4; an++)
                    mma_f16(acc[am][an], ah[am], bh[an]);
        }
        __syncthreads();
    }

    // ---- epilogue ----
#pragma unroll
    for (int am = 0; am < 4; am++) {
        const int row0 = bm + wm * 64 + am * 16 + g;
#pragma unroll
        for (int an = 0; an < 4; an++) {
            const int col = bn + wn * 32 + an * 8 + 2 * tg;
            const float v00 = acc[am][an][0] + bias[col];
            const float v01 = acc[am][an][1] + bias[col + 1];
            const float v10 = acc[am][an][2] + bias[col];
            const float v11 = acc[am][an][3] + bias[col + 1];
            if (MODE == 0) {
#pragma unroll
                for (int e = 0; e < 4; e++) {
                    const int m = (e < 2) ? row0 : row0 + 8;
                    const int n = col + (e & 1);
                    const float v = (e == 0) ? v00 : (e == 1) ? v01 : (e == 2) ? v10 : v11;
                    const int b = m >> 11;            // NS = 2048
                    const int srow = m & (NS - 1);
                    const int which = n >> 10;        // ND = 1024
                    const int dcol  = n & (ND - 1);
                    const int h  = dcol >> 6;         // NHD = 64
                    const int hd = dcol & 63;
                    const int bhh = b * NH + h;
                    if (which == 0) {
                        const size_t o = ((size_t)bhh * NS + srow) * NHD + hd;
                        g_qh[o] = __float2half_rn(v);
                    } else if (which == 1) {
                        __half hi, lo;
                        split_h(v, hi, lo);
                        const size_t o = ((size_t)bhh * NS + srow) * NHD + hd;
                        g_kh[o] = hi; g_kl[o] = lo;
                    } else {
                        const size_t o = ((size_t)bhh * NHD + hd) * NS + srow;
                        g_vh[o] = __float2half_rn(v);
                    }
                }
            } else {
                *(float2*)(C + (size_t)row0 * N + col)       = make_float2(v00, v01);
                *(float2*)(C + (size_t)(row0 + 8) * N + col) = make_float2(v10, v11);
            }
        }
    }
}

// ---------------------------------------------------------------------------
// FP16 tensor-core causal flash attention (unchanged from round 13).
// Q hi-only; K hi/lo (2-pass QK); V hi-only (1-pass PV).
// 128-row KV stages processed as two 64-col sub-tiles.
// CTA: 128 q rows, 256 threads = 8 warps (one m16 band each).
// ---------------------------------------------------------------------------
#define KST    72                        // K tile stride: 64 hd + 8 pad
#define VST    136                       // V tile stride: 128 kv + 8 pad
#define KTILE  (128 * KST)               // halves (128 kv rows x 64 hd)
#define VTILE  (64 * VST)                // halves (64 hd rows x 128 kv)
#define STG_H  (2 * KTILE + VTILE)       // Kh, Kl, Vh
#define ATTN_SMEM (2 * STG_H * 2)        // bytes = 108544

__global__ __launch_bounds__(256, 1) void attn_f16()
{
    extern __shared__ __half smh[];
    const int tid  = threadIdx.x;
    const int lane = tid & 31;
    const int w    = tid >> 5;
    const int g    = lane >> 2;
    const int tg   = lane & 3;
    const int qt   = 15 - blockIdx.x;      // heavy CTAs first
    const int bh   = blockIdx.y;
    const int qbase = qt * 128;

    const int la = lane & 7;
    const uint32_t boffK = (uint32_t)(((la + ((lane >> 4) & 1) * 8) * KST
                                      + ((lane >> 3) & 1) * 8) * 2);
    const uint32_t boffV = (uint32_t)(((la + ((lane >> 4) & 1) * 8) * VST
                                      + ((lane >> 3) & 1) * 8) * 2);

    const __half* Qh = g_qh + (size_t)bh * NS * NHD;
    const __half* Kh = g_kh + (size_t)bh * NS * NHD;
    const __half* Kl = g_kl + (size_t)bh * NS * NHD;
    const __half* Vh = g_vh + (size_t)bh * NHD * NS;

    const int r0 = qbase + w * 16 + g;     // global q row of accum row 0

    // Q fragments resident in registers (4 ksteps of k16)
    uint32_t qfh[4][4];
#pragma unroll
    for (int ks = 0; ks < 4; ks++) {
        const int kb = ks * 16;
        qfh[ks][0] = ldh2(Qh + (size_t)r0 * NHD + kb + 2 * tg);
        qfh[ks][1] = ldh2(Qh + (size_t)(r0 + 8) * NHD + kb + 2 * tg);
        qfh[ks][2] = ldh2(Qh + (size_t)r0 * NHD + kb + 8 + 2 * tg);
        qfh[ks][3] = ldh2(Qh + (size_t)(r0 + 8) * NHD + kb + 8 + 2 * tg);
    }

    float o[8][4];
#pragma unroll
    for (int j = 0; j < 8; j++)
#pragma unroll
        for (int c = 0; c < 4; c++) o[j][c] = 0.f;
    float m[2] = {-1e30f, -1e30f};
    float l[2] = {0.f, 0.f};

    const int nt = qt + 1;                  // 128-row KV stages

    auto load_tile = [&](int kt, int s) {
        __half* st = smh + s * STG_H;
        // Kh, Kl: 128 kv rows x 64 halves
#pragma unroll
        for (int i = 0; i < 4; i++) {
            const int idx = tid + i * 256;       // 0..1023
            const int row = idx >> 3;            // 0..127
            const int q   = idx & 7;
            const uint32_t d = smem_u32(st + row * KST + q * 8);
            cp_async16(d,             Kh + (size_t)(kt * 128 + row) * NHD + q * 8);
            cp_async16(d + KTILE * 2, Kl + (size_t)(kt * 128 + row) * NHD + q * 8);
        }
        // Vh: 64 hd rows x 128 halves
#pragma unroll
        for (int i = 0; i < 4; i++) {
            const int idx = tid + i * 256;       // 0..1023
            const int row = idx >> 4;            // 0..63
            const int q   = idx & 15;
            cp_async16(smem_u32(st + 2 * KTILE + row * VST + q * 8),
                       Vh + (size_t)row * NS + kt * 128 + q * 8);
        }
        CP_COMMIT();
    };

    load_tile(0, 0);

    for (int kt = 0; kt < nt; kt++) {
        const int s = kt & 1;
        __syncthreads();                        // all warps done with stage s^1
        if (kt + 1 < nt) {
            load_tile(kt + 1, s ^ 1);
            asm volatile("cp.async.wait_group 1;" ::: "memory");
        } else {
            asm volatile("cp.async.wait_group 0;" ::: "memory");
        }
        __syncthreads();                        // stage s visible to all

        const uint32_t sK = smem_u32(smh + s * STG_H);           // Kh (bytes)
        const uint32_t sV = sK + (uint32_t)(2 * KTILE * 2);      // Vh

#pragma unroll
        for (int st2 = 0; st2 < 2; st2++) {
            // On the diagonal stage, warps 0..3 have every column of sub-tile 1
            // masked — skip entirely.
            if (kt == nt - 1 && st2 == 1 && w < 4) continue;
            const int colbase = kt * 128 + st2 * 64;

            // ---- S = Q K^T : q_hi*k_hi fp32 acc; q_hi*k_lo fp16 acc ----
            float sc[8][4];
            uint32_t scch[8][2];
#pragma unroll
            for (int j = 0; j < 8; j++) {
#pragma unroll
                for (int c = 0; c < 4; c++) sc[j][c] = 0.f;
                scch[j][0] = 0u; scch[j][1] = 0u;
            }

#pragma unroll
            for (int ks = 0; ks < 4; ks++) {
                const int kb = ks * 16;
                uint32_t bfh[8][2], bfl[8][2];
#pragma unroll
                for (int p = 0; p < 4; p++) {
                    const uint32_t base = sK
                        + (uint32_t)((((st2 * 64 + p * 16) * KST) + kb) * 2);
                    ldsm_x4(bfh[2 * p][0], bfh[2 * p][1],
                            bfh[2 * p + 1][0], bfh[2 * p + 1][1], base + boffK);
                    ldsm_x4(bfl[2 * p][0], bfl[2 * p][1],
                            bfl[2 * p + 1][0], bfl[2 * p + 1][1],
                            base + (uint32_t)(KTILE * 2) + boffK);
                }
#pragma unroll
                for (int j = 0; j < 8; j++) mma_f16(sc[j], qfh[ks], bfh[j]);
#pragma unroll
                for (int j = 0; j < 8; j++) mma_f16acc(scch[j], qfh[ks], bfl[j]);
            }

            // ---- fold corrections, scale, causal mask ----
#pragma unroll
            for (int j = 0; j < 8; j++) {
                const float2 c01 = h2f2(scch[j][0]);
                const float2 c23 = h2f2(scch[j][1]);
                sc[j][0] = (sc[j][0] + c01.x) * SCALE;
                sc[j][1] = (sc[j][1] + c01.y) * SCALE;
                sc[j][2] = (sc[j][2] + c23.x) * SCALE;
                sc[j][3] = (sc[j][3] + c23.y) * SCALE;
            }
            if (kt == nt - 1) {
#pragma unroll
                for (int j = 0; j < 8; j++) {
                    const int c0 = colbase + j * 8 + 2 * tg;
#pragma unroll
                    for (int c = 0; c < 4; c++) {
                        const int col = c0 + (c & 1);
                        const int row = (c < 2) ? r0 : r0 + 8;
                        if (col > row) sc[j][c] = -1e30f;
                    }
                }
            }

            // ---- online softmax (FFMA exp) ----
#pragma unroll
            for (int r = 0; r < 2; r++) {
                float rm = -1e30f;
#pragma unroll
                for (int j = 0; j < 8; j++)
                    rm = fmaxf(rm, fmaxf(sc[j][2 * r], sc[j][2 * r + 1]));
                rm = fmaxf(rm, __shfl_xor_sync(0xffffffffu, rm, 1));
                rm = fmaxf(rm, __shfl_xor_sync(0xffffffffu, rm, 2));
                const float mn   = fmaxf(m[r], rm);
                const float corr = fexp(m[r] - mn);
                m[r] = mn;
                float ps = 0.f;
#pragma unroll
                for (int j = 0; j < 8; j++) {
                    const float p0 = fexp(sc[j][2 * r]     - mn);
                    const float p1 = fexp(sc[j][2 * r + 1] - mn);
                    sc[j][2 * r]     = p0;
                    sc[j][2 * r + 1] = p1;
                    ps += p0 + p1;
                }
                l[r] = l[r] * corr + ps;
#pragma unroll
                for (int j = 0; j < 8; j++) {
                    o[j][2 * r]     *= corr;
                    o[j][2 * r + 1] *= corr;
                }
            }

            // ---- O += P V  (single fp32 pass) ----
#pragma unroll
            for (int ks = 0; ks < 4; ks++) {
                const int kb = ks * 16;
                uint32_t pa[4];
                pa[0] = pack_h2(sc[2 * ks][0],     sc[2 * ks][1]);
                pa[1] = pack_h2(sc[2 * ks][2],     sc[2 * ks][3]);
                pa[2] = pack_h2(sc[2 * ks + 1][0], sc[2 * ks + 1][1]);
                pa[3] = pack_h2(sc[2 * ks + 1][2], sc[2 * ks + 1][3]);
                uint32_t vfh[8][2];
#pragma unroll
                for (int p = 0; p < 4; p++) {
                    const uint32_t base = sV
                        + (uint32_t)(((p * 16) * VST + st2 * 64 + kb) * 2);
                    ldsm_x4(vfh[2 * p][0], vfh[2 * p][1],
                            vfh[2 * p + 1][0], vfh[2 * p + 1][1], base + boffV);
                }
#pragma unroll
                for (int j = 0; j < 8; j++) mma_f16(o[j], pa, vfh[j]);
            }
        }
    }

    // ---- finalize: normalize, convert to fp16, write [b,s,d] (hi only) ----
#pragma unroll
    for (int r = 0; r < 2; r++) {
        float lv = l[r];
        lv += __shfl_xor_sync(0xffffffffu, lv, 1);
        lv += __shfl_xor_sync(0xffffffffu, lv, 2);
        l[r] = 1.0f / lv;
    }
    const int b = bh >> 4;
    const int h = bh & (NH - 1);
#pragma unroll
    for (int j = 0; j < 8; j++) {
        const int col = h * NHD + j * 8 + 2 * tg;
#pragma unroll
        for (int r = 0; r < 2; r++) {
            const int row = (r == 0) ? r0 : r0 + 8;
            const size_t off = ((size_t)(b * NS) + row) * ND + col;
            *(uint32_t*)(g_axh + off) = pack_h2(o[j][2 * r] * l[r], o[j][2 * r + 1] * l[r]);
        }
    }
}

// ---------------------------------------------------------------------------
// kernel_launch
// ---------------------------------------------------------------------------
extern "C" void kernel_launch(void* const* d_in, const int* in_sizes, int n_in,
                              void* d_out, int out_size)
{
    (void)in_sizes; (void)n_in; (void)out_size;
    const float* x     = (const float*)d_in[0];
    const float* Wqkv  = (const float*)d_in[1];
    const float* bqkv  = (const float*)d_in[2];
    const float* Wproj = (const float*)d_in[3];
    const float* bproj = (const float*)d_in[4];
    float* out = (float*)d_out;

    void *p_axh, *p_wqh, *p_wph;
    cudaGetSymbolAddress(&p_axh, g_axh);
    cudaGetSymbolAddress(&p_wqh, g_wqh);
    cudaGetSymbolAddress(&p_wph, g_wph);
    __half* axh = (__half*)p_axh;
    __half* wqh = (__half*)p_wqh;
    __half* wph = (__half*)p_wph;

    static bool attr_done = false;
    if (!attr_done) {
        cudaFuncSetAttribute((const void*)gemm_f16<0>,
                             cudaFuncAttributeMaxDynamicSharedMemorySize, GEMM_SMEM);
        cudaFuncSetAttribute((const void*)gemm_f16<1>,
                             cudaFuncAttributeMaxDynamicSharedMemorySize, GEMM_SMEM);
        cudaFuncSetAttribute((const void*)attn_f16,
                             cudaFuncAttributeMaxDynamicSharedMemorySize, ATTN_SMEM);
        attr_done = true;
    }

    // 0) weight transpose + fp16 convert
    {
        dim3 b(32, 8);
        tconv16_kernel<<<dim3(3 * ND / 32, ND / 32), b>>>(Wqkv, wqh, ND, 3 * ND);
        tconv16_kernel<<<dim3(ND / 32, ND / 32), b>>>(Wproj, wph, ND, ND);
    }

    // 1) convert x to fp16
    convert16_kernel<<<2048, 256>>>(x, axh, NB * NS * ND);

    // 2) QKV GEMM -> scatter q (hi) / k (hi+lo) / v (hi, transposed)
    gemm_f16<0><<<dim3(3 * ND / 128, NB * NS / 128), 256, GEMM_SMEM>>>(
        axh, wqh, bqkv, nullptr, NB * NS, 3 * ND, ND);

    // 3) fp16 tensor-core causal flash attention -> g_axh
    attn_f16<<<dim3(NS / 128, NB * NH), 256, ATTN_SMEM>>>();

    // 4) output projection -> d_out
    gemm_f16<1><<<dim3(ND / 128, NB * NS / 128), 256, GEMM_SMEM>>>(
        axh, wph, bproj, out, NB * NS, ND, ND);
}

// round 15
// speedup vs baseline: 2.0125x; 1.2034x over previous
#include <cuda_runtime.h>
#include <cuda_fp16.h>
#include <math.h>
#include <stdint.h>

// Problem constants
#define NB  2
#define NS  2048
#define ND  1024
#define NH  16
#define NHD 64
#define SCALE  0.125f    // 1/sqrt(64), applied to scores post-MMA

// ---------------------------------------------------------------------------
// Scratch (allocation-free contract: __device__ globals)
// ---------------------------------------------------------------------------
__device__ __half g_qh[NB * NH * NS * NHD];   // [bh][s][hd]  (unscaled)
__device__ __half g_kh[NB * NH * NS * NHD];   // [bh][s][hd]
__device__ __half g_vh[NB * NH * NS * NHD];   // [bh][hd][s]  (transposed)
__device__ __half g_axh[NB * NS * ND];        // activations (x, then attn out)
__device__ __half g_wqh[3 * ND * ND];         // W_qkv^T fp16  [3072 x 1024]
__device__ __half g_wph[ND * ND];             // W_proj^T fp16 [1024 x 1024]

// ---------------------------------------------------------------------------
// Helpers
// ---------------------------------------------------------------------------
__device__ __forceinline__ uint32_t smem_u32(const void* p) {
    uint32_t a;
    asm("{ .reg .u64 t; cvta.to.shared.u64 t, %1; cvt.u32.u64 %0, t; }"
        : "=r"(a) : "l"(p));
    return a;
}

__device__ __forceinline__ void cp_async16(uint32_t saddr, const void* gptr) {
    asm volatile("cp.async.cg.shared.global [%0], [%1], 16;" :: "r"(saddr), "l"(gptr));
}
#define CP_COMMIT() asm volatile("cp.async.commit_group;" ::: "memory")

__device__ __forceinline__ uint32_t ldh2(const __half* p) {
    return *reinterpret_cast<const uint32_t*>(p);
}

__device__ __forceinline__ uint32_t pack_h2(float a, float b) {
    __half2 h = __floats2half2_rn(a, b);
    return *reinterpret_cast<uint32_t*>(&h);
}

// ldmatrix: 4x (8x8 b16) tiles; per-lane row addresses
__device__ __forceinline__ void ldsm_x4(uint32_t& r0, uint32_t& r1,
                                        uint32_t& r2, uint32_t& r3, uint32_t addr) {
    asm volatile("ldmatrix.sync.aligned.m8n8.x4.shared.b16 {%0,%1,%2,%3}, [%4];"
        : "=r"(r0), "=r"(r1), "=r"(r2), "=r"(r3) : "r"(addr));
}

// m16n8k16 f16 MMA, fp32 accumulate in-place
__device__ __forceinline__ void mma_f16(float* d, const uint32_t* a, const uint32_t* b) {
    asm volatile(
        "mma.sync.aligned.m16n8k16.row.col.f32.f16.f16.f32 "
        "{%0,%1,%2,%3}, {%4,%5,%6,%7}, {%8,%9}, {%0,%1,%2,%3};"
        : "+f"(d[0]), "+f"(d[1]), "+f"(d[2]), "+f"(d[3])
        : "r"(a[0]), "r"(a[1]), "r"(a[2]), "r"(a[3]), "r"(b[0]), "r"(b[1]));
}

// FFMA-only exp (finite x; clamp handles big negatives). rel err ~2.4e-6.
__device__ __forceinline__ float fexp(float x) {
    x = fmaxf(x, -60.0f);
    const float y = x * 1.44269504f;
    const float t = y + 12582912.0f;              // 1.5 * 2^23
    const int   n = __float_as_int(t) - 0x4B400000;
    const float f = y - (t - 12582912.0f);
    float p = 1.33335581e-3f;
    p = fmaf(p, f, 9.61812910e-3f);
    p = fmaf(p, f, 5.55041087e-2f);
    p = fmaf(p, f, 2.40226510e-1f);
    p = fmaf(p, f, 6.93147182e-1f);
    p = fmaf(p, f, 1.0f);
    return __int_as_float(__float_as_int(p) + (n << 23));
}

// ---------------------------------------------------------------------------
// Prep kernels
// ---------------------------------------------------------------------------
__global__ void convert16_kernel(const float* __restrict__ in,
                                 __half* __restrict__ hi, int n) {
    for (int i = blockIdx.x * blockDim.x + threadIdx.x; i < n; i += gridDim.x * blockDim.x)
        hi[i] = __float2half_rn(in[i]);
}

// W [K,N] row-major -> T [N,K] row-major, fp16
__global__ __launch_bounds__(256) void tconv16_kernel(
    const float* __restrict__ W, __half* __restrict__ Thi, int K, int N) {
    __shared__ float tile[32][33];
    const int tx = threadIdx.x;
    const int ty = threadIdx.y;
    const int n0 = blockIdx.x * 32;
    const int k0 = blockIdx.y * 32;
#pragma unroll
    for (int i = 0; i < 32; i += 8)
        tile[ty + i][tx] = W[(size_t)(k0 + ty + i) * N + n0 + tx];
    __syncthreads();
#pragma unroll
    for (int i = 0; i < 32; i += 8)
        Thi[(size_t)(n0 + ty + i) * K + k0 + tx] = __float2half_rn(tile[tx][ty + i]);
}

// ---------------------------------------------------------------------------
// Pure FP16 mma.sync GEMM (single pass, fp32 acc): C = A * B^T + bias.
// 128x128/CTA, 256 threads, warps 2(m) x 4(n), warp tile 64x32, KC 128
// (8 sync iterations instead of 16), double-buffered cp.async.
// MODE 0: scatter QKV (q; k; v transposed);  MODE 1: fp32 C.
// ---------------------------------------------------------------------------
#define KC     128
#define ROWH   136                      // 128 + 8 halves pad
#define TILEH  (128 * ROWH)             // halves per tile
#define STAGEH (2 * TILEH)              // A, B
#define GEMM_SMEM (2 * STAGEH * 2)      // bytes = 139264

template <int MODE>
__global__ __launch_bounds__(256, 1) void gemm_f16(
    const __half* __restrict__ Ahi, const __half* __restrict__ Bhi,
    const float* __restrict__ bias, float* __restrict__ C,
    int M, int N, int K)
{
    extern __shared__ __half smh[];
    const int tid  = threadIdx.x;
    const int lane = tid & 31;
    const int wid  = tid >> 5;
    const int wm   = wid >> 2;
    const int wn   = wid & 3;
    const int g    = lane >> 2;
    const int tg   = lane & 3;
    const int bm = blockIdx.y * 128;
    const int bn = blockIdx.x * 128;

    // ldmatrix per-lane byte offsets (within a 16x16 tile at given base)
    const int la = lane & 7;
    const uint32_t aoff = (uint32_t)(((la + ((lane >> 3) & 1) * 8) * ROWH
                                     + ((lane >> 4) & 1) * 8) * 2);
    const uint32_t boff = (uint32_t)(((la + ((lane >> 4) & 1) * 8) * ROWH
                                     + ((lane >> 3) & 1) * 8) * 2);

    auto load_stage = [&](int c, int s) {
        const int k0 = c * KC;
        __half* stage = smh + s * STAGEH;
#pragma unroll
        for (int t = 0; t < 2; t++) {
            const __half* src = (t == 0) ? Ahi : Bhi;
            const int rbase = (t == 0) ? bm : bn;
            __half* dst = stage + t * TILEH;
#pragma unroll
            for (int i = 0; i < 8; i++) {
                const int idx = tid + i * 256;     // 0..2047
                const int r = idx >> 4;            // 0..127
                const int q = idx & 15;            // 16 chunks of 8 halves
                cp_async16(smem_u32(dst + r * ROWH + q * 8),
                           src + (size_t)(rbase + r) * K + k0 + q * 8);
            }
        }
        CP_COMMIT();
    };

    float acc[4][4][4];
#pragma unroll
    for (int i = 0; i < 4; i++)
#pragma unroll
        for (int j = 0; j < 4; j++)
#pragma unroll
            for (int kq = 0; kq < 4; kq++) acc[i][j][kq] = 0.f;

    const int NCH = K / KC;
    load_stage(0, 0);

    for (int c = 0; c < NCH; c++) {
        const int s = c & 1;
        if (c + 1 < NCH) {
            load_stage(c + 1, (c + 1) & 1);
            asm volatile("cp.async.wait_group 1;" ::: "memory");
        } else {
            asm volatile("cp.async.wait_group 0;" ::: "memory");
        }
        __syncthreads();

        const uint32_t sA = smem_u32(smh + s * STAGEH);          // A (bytes)
        const uint32_t sB = sA + (uint32_t)(TILEH * 2);          // B

#pragma unroll
        for (int ks = 0; ks < 8; ks++) {
            const int kb = ks * 16;
            uint32_t ah[4][4], bh[4][2];
#pragma unroll
            for (int am = 0; am < 4; am++) {
                const uint32_t base = sA + (uint32_t)(((wm * 64 + am * 16) * ROWH + kb) * 2);
                ldsm_x4(ah[am][0], ah[am][1], ah[am][2], ah[am][3], base + aoff);
            }
#pragma unroll
            for (int p = 0; p < 2; p++) {
                const uint32_t base = sB + (uint32_t)(((wn * 32 + p * 16) * ROWH + kb) * 2);
                ldsm_x4(bh[2 * p][0], bh[2 * p][1], bh[2 * p + 1][0], bh[2 * p + 1][1],
                        base + boff);
            }
#pragma unroll
            for (int am = 0; am < 4; am++)
#pragma unroll
                for (int an = 0; an < 4; an++)
                    mma_f16(acc[am][an], ah[am], bh[an]);
        }
        __syncthreads();
    }

    // ---- epilogue ----
#pragma unroll
    for (int am = 0; am < 4; am++) {
        const int row0 = bm + wm * 64 + am * 16 + g;
#pragma unroll
        for (int an = 0; an < 4; an++) {
            const int col = bn + wn * 32 + an * 8 + 2 * tg;
            const float v00 = acc[am][an][0] + bias[col];
            const float v01 = acc[am][an][1] + bias[col + 1];
            const float v10 = acc[am][an][2] + bias[col];
            const float v11 = acc[am][an][3] + bias[col + 1];
            if (MODE == 0) {
#pragma unroll
                for (int e = 0; e < 4; e++) {
                    const int m = (e < 2) ? row0 : row0 + 8;
                    const int n = col + (e & 1);
                    const float v = (e == 0) ? v00 : (e == 1) ? v01 : (e == 2) ? v10 : v11;
                    const int b = m >> 11;            // NS = 2048
                    const int srow = m & (NS - 1);
                    const int which = n >> 10;        // ND = 1024
                    const int dcol  = n & (ND - 1);
                    const int h  = dcol >> 6;         // NHD = 64
                    const int hd = dcol & 63;
                    const int bhh = b * NH + h;
                    const __half hv = __float2half_rn(v);
                    if (which == 0) {
                        g_qh[((size_t)bhh * NS + srow) * NHD + hd] = hv;
                    } else if (which == 1) {
                        g_kh[((size_t)bhh * NS + srow) * NHD + hd] = hv;
                    } else {
                        g_vh[((size_t)bhh * NHD + hd) * NS + srow] = hv;
                    }
                }
            } else {
                *(float2*)(C + (size_t)row0 * N + col)       = make_float2(v00, v01);
                *(float2*)(C + (size_t)(row0 + 8) * N + col) = make_float2(v10, v11);
            }
        }
    }
}

// ---------------------------------------------------------------------------
// Pure FP16 tensor-core causal flash attention (no correction passes).
// 128-row KV stages processed as two 64-col sub-tiles.
// CTA: 128 q rows, 256 threads = 8 warps (one m16 band each).
// ---------------------------------------------------------------------------
#define KST    72                        // K tile stride: 64 hd + 8 pad
#define VST    136                       // V tile stride: 128 kv + 8 pad
#define KTILE  (128 * KST)               // halves (128 kv rows x 64 hd)
#define VTILE  (64 * VST)                // halves (64 hd rows x 128 kv)
#define STG_H  (KTILE + VTILE)           // Kh, Vh
#define ATTN_SMEM (2 * STG_H * 2)        // bytes = 71680

__global__ __launch_bounds__(256, 1) void attn_f16()
{
    extern __shared__ __half smh[];
    const int tid  = threadIdx.x;
    const int lane = tid & 31;
    const int w    = tid >> 5;
    const int g    = lane >> 2;
    const int tg   = lane & 3;
    const int qt   = 15 - blockIdx.x;      // heavy CTAs first
    const int bh   = blockIdx.y;
    const int qbase = qt * 128;

    const int la = lane & 7;
    const uint32_t boffK = (uint32_t)(((la + ((lane >> 4) & 1) * 8) * KST
                                      + ((lane >> 3) & 1) * 8) * 2);
    const uint32_t boffV = (uint32_t)(((la + ((lane >> 4) & 1) * 8) * VST
                                      + ((lane >> 3) & 1) * 8) * 2);

    const __half* Qh = g_qh + (size_t)bh * NS * NHD;
    const __half* Kh = g_kh + (size_t)bh * NS * NHD;
    const __half* Vh = g_vh + (size_t)bh * NHD * NS;

    const int r0 = qbase + w * 16 + g;     // global q row of accum row 0

    // Q fragments resident in registers (4 ksteps of k16)
    uint32_t qfh[4][4];
#pragma unroll
    for (int ks = 0; ks < 4; ks++) {
        const int kb = ks * 16;
        qfh[ks][0] = ldh2(Qh + (size_t)r0 * NHD + kb + 2 * tg);
        qfh[ks][1] = ldh2(Qh + (size_t)(r0 + 8) * NHD + kb + 2 * tg);
        qfh[ks][2] = ldh2(Qh + (size_t)r0 * NHD + kb + 8 + 2 * tg);
        qfh[ks][3] = ldh2(Qh + (size_t)(r0 + 8) * NHD + kb + 8 + 2 * tg);
    }

    float o[8][4];
#pragma unroll
    for (int j = 0; j < 8; j++)
#pragma unroll
        for (int c = 0; c < 4; c++) o[j][c] = 0.f;
    float m[2] = {-1e30f, -1e30f};
    float l[2] = {0.f, 0.f};

    const int nt = qt + 1;                  // 128-row KV stages

    auto load_tile = [&](int kt, int s) {
        __half* st = smh + s * STG_H;
        // Kh: 128 kv rows x 64 halves
#pragma unroll
        for (int i = 0; i < 4; i++) {
            const int idx = tid + i * 256;       // 0..1023
            const int row = idx >> 3;            // 0..127
            const int q   = idx & 7;
            cp_async16(smem_u32(st + row * KST + q * 8),
                       Kh + (size_t)(kt * 128 + row) * NHD + q * 8);
        }
        // Vh: 64 hd rows x 128 halves
#pragma unroll
        for (int i = 0; i < 4; i++) {
            const int idx = tid + i * 256;       // 0..1023
            const int row = idx >> 4;            // 0..63
            const int q   = idx & 15;
            cp_async16(smem_u32(st + KTILE + row * VST + q * 8),
                       Vh + (size_t)row * NS + kt * 128 + q * 8);
        }
        CP_COMMIT();
    };

    load_tile(0, 0);

    for (int kt = 0; kt < nt; kt++) {
        const int s = kt & 1;
        __syncthreads();                        // all warps done with stage s^1
        if (kt + 1 < nt) {
            load_tile(kt + 1, s ^ 1);
            asm volatile("cp.async.wait_group 1;" ::: "memory");
        } else {
            asm volatile("cp.async.wait_group 0;" ::: "memory");
        }
        __syncthreads();                        // stage s visible to all

        const uint32_t sK = smem_u32(smh + s * STG_H);           // Kh (bytes)
        const uint32_t sV = sK + (uint32_t)(KTILE * 2);          // Vh

#pragma unroll
        for (int st2 = 0; st2 < 2; st2++) {
            // On the diagonal stage, warps 0..3 have every column of sub-tile 1
            // masked — skip entirely.
            if (kt == nt - 1 && st2 == 1 && w < 4) continue;
            const int colbase = kt * 128 + st2 * 64;

            // ---- S = Q K^T (fp32 acc) ----
            float sc[8][4];
#pragma unroll
            for (int j = 0; j < 8; j++)
#pragma unroll
                for (int c = 0; c < 4; c++) sc[j][c] = 0.f;

#pragma unroll
            for (int ks = 0; ks < 4; ks++) {
                const int kb = ks * 16;
                uint32_t bfh[8][2];
#pragma unroll
                for (int p = 0; p < 4; p++) {
                    const uint32_t base = sK
                        + (uint32_t)((((st2 * 64 + p * 16) * KST) + kb) * 2);
                    ldsm_x4(bfh[2 * p][0], bfh[2 * p][1],
                            bfh[2 * p + 1][0], bfh[2 * p + 1][1], base + boffK);
                }
#pragma unroll
                for (int j = 0; j < 8; j++) mma_f16(sc[j], qfh[ks], bfh[j]);
            }

            // ---- scale, causal mask ----
#pragma unroll
            for (int j = 0; j < 8; j++)
#pragma unroll
                for (int c = 0; c < 4; c++) sc[j][c] *= SCALE;
            if (kt == nt - 1) {
#pragma unroll
                for (int j = 0; j < 8; j++) {
                    const int c0 = colbase + j * 8 + 2 * tg;
#pragma unroll
                    for (int c = 0; c < 4; c++) {
                        const int col = c0 + (c & 1);
                        const int row = (c < 2) ? r0 : r0 + 8;
                        if (col > row) sc[j][c] = -1e30f;
                    }
                }
            }

            // ---- online softmax (FFMA exp) ----
#pragma unroll
            for (int r = 0; r < 2; r++) {
                float rm = -1e30f;
#pragma unroll
                for (int j = 0; j < 8; j++)
                    rm = fmaxf(rm, fmaxf(sc[j][2 * r], sc[j][2 * r + 1]));
                rm = fmaxf(rm, __shfl_xor_sync(0xffffffffu, rm, 1));
                rm = fmaxf(rm, __shfl_xor_sync(0xffffffffu, rm, 2));
                const float mn   = fmaxf(m[r], rm);
                const float corr = fexp(m[r] - mn);
                m[r] = mn;
                float ps = 0.f;
#pragma unroll
                for (int j = 0; j < 8; j++) {
                    const float p0 = fexp(sc[j][2 * r]     - mn);
                    const float p1 = fexp(sc[j][2 * r + 1] - mn);
                    sc[j][2 * r]     = p0;
                    sc[j][2 * r + 1] = p1;
                    ps += p0 + p1;
                }
                l[r] = l[r] * corr + ps;
#pragma unroll
                for (int j = 0; j < 8; j++) {
                    o[j][2 * r]     *= corr;
                    o[j][2 * r + 1] *= corr;
                }
            }

            // ---- O += P V ----
#pragma unroll
            for (int ks = 0; ks < 4; ks++) {
                const int kb = ks * 16;
                uint32_t pa[4];
                pa[0] = pack_h2(sc[2 * ks][0],     sc[2 * ks][1]);
                pa[1] = pack_h2(sc[2 * ks][2],     sc[2 * ks][3]);
                pa[2] = pack_h2(sc[2 * ks + 1][0], sc[2 * ks + 1][1]);
                pa[3] = pack_h2(sc[2 * ks + 1][2], sc[2 * ks + 1][3]);
                uint32_t vfh[8][2];
#pragma unroll
                for (int p = 0; p < 4; p++) {
                    const uint32_t base = sV
                        + (uint32_t)(((p * 16) * VST + st2 * 64 + kb) * 2);
                    ldsm_x4(vfh[2 * p][0], vfh[2 * p][1],
                            vfh[2 * p + 1][0], vfh[2 * p + 1][1], base + boffV);
                }
#pragma unroll
                for (int j = 0; j < 8; j++) mma_f16(o[j], pa, vfh[j]);
            }
        }
    }

    // ---- finalize: normalize, convert to fp16, write [b,s,d] ----
#pragma unroll
    for (int r = 0; r < 2; r++) {
        float lv = l[r];
        lv += __shfl_xor_sync(0xffffffffu, lv, 1);
        lv += __shfl_xor_sync(0xffffffffu, lv, 2);
        l[r] = 1.0f / lv;
    }
    const int b = bh >> 4;
    const int h = bh & (NH - 1);
#pragma unroll
    for (int j = 0; j < 8; j++) {
        const int col = h * NHD + j * 8 + 2 * tg;
#pragma unroll
        for (int r = 0; r < 2; r++) {
            const int row = (r == 0) ? r0 : r0 + 8;
            const size_t off = ((size_t)(b * NS) + row) * ND + col;
            *(uint32_t*)(g_axh + off) = pack_h2(o[j][2 * r] * l[r], o[j][2 * r + 1] * l[r]);
        }
    }
}

// ---------------------------------------------------------------------------
// kernel_launch
// ---------------------------------------------------------------------------
extern "C" void kernel_launch(void* const* d_in, const int* in_sizes, int n_in,
                              void* d_out, int out_size)
{
    (void)in_sizes; (void)n_in; (void)out_size;
    const float* x     = (const float*)d_in[0];
    const float* Wqkv  = (const float*)d_in[1];
    const float* bqkv  = (const float*)d_in[2];
    const float* Wproj = (const float*)d_in[3];
    const float* bproj = (const float*)d_in[4];
    float* out = (float*)d_out;

    void *p_axh, *p_wqh, *p_wph;
    cudaGetSymbolAddress(&p_axh, g_axh);
    cudaGetSymbolAddress(&p_wqh, g_wqh);
    cudaGetSymbolAddress(&p_wph, g_wph);
    __half* axh = (__half*)p_axh;
    __half* wqh = (__half*)p_wqh;
    __half* wph = (__half*)p_wph;

    static bool attr_done = false;
    if (!attr_done) {
        cudaFuncSetAttribute((const void*)gemm_f16<0>,
                             cudaFuncAttributeMaxDynamicSharedMemorySize, GEMM_SMEM);
        cudaFuncSetAttribute((const void*)gemm_f16<1>,
                             cudaFuncAttributeMaxDynamicSharedMemorySize, GEMM_SMEM);
        cudaFuncSetAttribute((const void*)attn_f16,
                             cudaFuncAttributeMaxDynamicSharedMemorySize, ATTN_SMEM);
        attr_done = true;
    }

    // 0) weight transpose + fp16 convert
    {
        dim3 b(32, 8);
        tconv16_kernel<<<dim3(3 * ND / 32, ND / 32), b>>>(Wqkv, wqh, ND, 3 * ND);
        tconv16_kernel<<<dim3(ND / 32, ND / 32), b>>>(Wproj, wph, ND, ND);
    }

    // 1) convert x to fp16
    convert16_kernel<<<2048, 256>>>(x, axh, NB * NS * ND);

    // 2) QKV GEMM -> scatter q / k / v (v transposed)
    gemm_f16<0><<<dim3(3 * ND / 128, NB * NS / 128), 256, GEMM_SMEM>>>(
        axh, wqh, bqkv, nullptr, NB * NS, 3 * ND, ND);

    // 3) fp16 tensor-core causal flash attention -> g_axh
    attn_f16<<<dim3(NS / 128, NB * NH), 256, ATTN_SMEM>>>();

    // 4) output projection -> d_out
    gemm_f16<1><<<dim3(ND / 128, NB * NS / 128), 256, GEMM_SMEM>>>(
        axh, wph, bproj, out, NB * NS, ND, ND);
}